// round 10
// baseline (speedup 1.0000x reference)
#include <cuda_runtime.h>
#include <cuda_fp16.h>
#include <math.h>
#include <stddef.h>
#include <stdint.h>

// ---------------- problem constants ----------------
#define BB     2
#define SS     2048
#define DIMM   2048
#define HEADS  16
#define HD     128
#define FFN    8192
#define CTX    512
#define M1     (BB*SS)
#define MC     (BB*CTX)
#define EMSTR  (6*DIMM)
#define EPSF   1e-6f

// ---------------- device scratch ----------------
__device__ float g_em [BB*6*DIMM];
__device__ float g_cos[SS*(HD/2)];
__device__ float g_sin[SS*(HD/2)];
__device__ float g_x  [M1*DIMM];
__device__ __align__(128) __half g_tmp[M1*DIMM];     // pre-norm q/k (fp16)
__device__ __align__(128) __half g_qh [BB*HEADS*SS*HD];
__device__ __align__(128) __half g_kh [BB*HEADS*SS*HD];
__device__ __align__(128) __half g_vh [M1*DIMM];
__device__ __align__(128) __half g_xn [M1*DIMM];
__device__ __align__(128) __half g_y  [M1*DIMM];
__device__ __align__(128) __half g_h  [(size_t)M1*FFN];
__device__ __align__(128) __half g_ctx[MC*DIMM];
__device__ __align__(128) __half g_wt [64*1024*1024];

#define WT_Q   ((size_t)0)
#define WT_K   ((size_t)4*1024*1024)
#define WT_V   ((size_t)8*1024*1024)
#define WT_O   ((size_t)12*1024*1024)
#define WT_CQ  ((size_t)16*1024*1024)
#define WT_CK  ((size_t)20*1024*1024)
#define WT_CV  ((size_t)24*1024*1024)
#define WT_CO  ((size_t)28*1024*1024)
#define WT_F1  ((size_t)32*1024*1024)
#define WT_F2  ((size_t)48*1024*1024)

// ---------------- helpers ----------------
__device__ __forceinline__ void cp16(void* smem, const void* g) {
    unsigned s = (unsigned)__cvta_generic_to_shared(smem);
    asm volatile("cp.async.cg.shared.global [%0], [%1], 16;\n" :: "r"(s), "l"(g));
}
__device__ __forceinline__ void cp_commit() { asm volatile("cp.async.commit_group;\n"); }
__device__ __forceinline__ void cp_wait0()  { asm volatile("cp.async.wait_group 0;\n"); }
__device__ __forceinline__ void cp_wait1()  { asm volatile("cp.async.wait_group 1;\n"); }

__device__ __forceinline__ void mma16816(float* d, const unsigned* a, const unsigned* b) {
    asm volatile(
        "mma.sync.aligned.m16n8k16.row.col.f32.f16.f16.f32 "
        "{%0,%1,%2,%3}, {%4,%5,%6,%7}, {%8,%9}, {%0,%1,%2,%3};\n"
        : "+f"(d[0]), "+f"(d[1]), "+f"(d[2]), "+f"(d[3])
        : "r"(a[0]), "r"(a[1]), "r"(a[2]), "r"(a[3]), "r"(b[0]), "r"(b[1]));
}
__device__ __forceinline__ void ldsm4(unsigned* r, unsigned saddr) {
    asm volatile("ldmatrix.sync.aligned.m8n8.x4.shared.b16 {%0,%1,%2,%3}, [%4];\n"
                 : "=r"(r[0]), "=r"(r[1]), "=r"(r[2]), "=r"(r[3]) : "r"(saddr));
}
__device__ __forceinline__ void ldsm4t(unsigned& r0, unsigned& r1, unsigned& r2, unsigned& r3,
                                       unsigned saddr) {
    asm volatile("ldmatrix.sync.aligned.m8n8.x4.trans.shared.b16 {%0,%1,%2,%3}, [%4];\n"
                 : "=r"(r0), "=r"(r1), "=r"(r2), "=r"(r3) : "r"(saddr));
}
__device__ __forceinline__ unsigned packh2(float a, float b) {
    __half2 h = __floats2half2_rn(a, b);
    return *reinterpret_cast<unsigned*>(&h);
}

template<typename OT> __device__ __forceinline__ void stv(OT* p, float v);
template<> __device__ __forceinline__ void stv<float >(float*  p, float v) { *p = v; }
template<> __device__ __forceinline__ void stv<__half>(__half* p, float v) { *p = __float2half(v); }

// ---------------- small kernels ----------------
__global__ void k_embed(const float* __restrict__ mo, const float* __restrict__ e,
                        float* __restrict__ em) {
    int i = blockIdx.x*256 + threadIdx.x;
    if (i < BB*6*DIMM) em[i] = mo[i % EMSTR] + e[i];
}

__global__ void k_ropetab(const float* __restrict__ fc, const float* __restrict__ fs,
                          float* __restrict__ cb, float* __restrict__ sb) {
    int i = blockIdx.x*256 + threadIdx.x;
    if (i >= SS*64) return;
    int s = i >> 6, d = i & 63;
    int f = s >> 8, h = (s >> 4) & 15, w = s & 15;
    int row = (d < 22) ? f : ((d < 43) ? h : w);
    cb[i] = fc[row*64 + d];
    sb[i] = fs[row*64 + d];
}

// vectorized fp32 -> fp16 convert (8 elems/thread)
__global__ void k_h8(const float* __restrict__ in, __half* __restrict__ out, int n) {
    int i = (blockIdx.x*256 + threadIdx.x)*8;
    if (i < n) {
        float4 a = *(const float4*)(in + i);
        float4 b = *(const float4*)(in + i + 4);
        __half2 h0 = __floats2half2_rn(a.x, a.y), h1 = __floats2half2_rn(a.z, a.w);
        __half2 h2 = __floats2half2_rn(b.x, b.y), h3 = __floats2half2_rn(b.z, b.w);
        uint4 u;
        u.x = *(unsigned*)&h0; u.y = *(unsigned*)&h1;
        u.z = *(unsigned*)&h2; u.w = *(unsigned*)&h3;
        *(uint4*)(out + i) = u;
    }
}

__global__ void k_ln(const float* __restrict__ x, const float* __restrict__ scv,
                     const float* __restrict__ shv, int em_mode, __half* __restrict__ out) {
    __shared__ float buf[DIMM];
    __shared__ float red[256];
    __shared__ float s_m, s_inv;
    int row = blockIdx.x, tid = threadIdx.x;
    const float* xr = x + (size_t)row*DIMM;
    float ls = 0.f;
    for (int c = tid; c < DIMM; c += 256) { float v = xr[c]; buf[c] = v; ls += v; }
    red[tid] = ls; __syncthreads();
    for (int s2 = 128; s2 > 0; s2 >>= 1) { if (tid < s2) red[tid] += red[tid+s2]; __syncthreads(); }
    if (tid == 0) s_m = red[0] * (1.f/DIMM);
    __syncthreads();
    float m = s_m, lv = 0.f;
    for (int c = tid; c < DIMM; c += 256) { float d = buf[c]-m; lv += d*d; }
    red[tid] = lv; __syncthreads();
    for (int s2 = 128; s2 > 0; s2 >>= 1) { if (tid < s2) red[tid] += red[tid+s2]; __syncthreads(); }
    if (tid == 0) s_inv = rsqrtf(red[0]*(1.f/DIMM) + EPSF);
    __syncthreads();
    float inv = s_inv;
    int bo = (row >> 11) * EMSTR;
    __half* orow = out + (size_t)row*DIMM;
    for (int c = tid; c < DIMM; c += 256) {
        float sc, sh;
        if (em_mode) { sc = 1.f + scv[bo+c]; sh = shv[bo+c]; }
        else         { sc = scv[c];          sh = shv[c];    }
        orow[c] = __float2half((buf[c]-m)*inv*sc + sh);
    }
}

// RMS norm (fp16 input) + optional RoPE + transpose to [B,H,L,HD]
__global__ void k_rms_t(const __half* __restrict__ in, const float* __restrict__ w,
                        __half* __restrict__ outT, int L, int do_rope, float oscale) {
    __shared__ float buf[DIMM];
    __shared__ float red[256];
    __shared__ float s_inv;
    int row = blockIdx.x, tid = threadIdx.x;
    int b = row / L, s = row % L;
    const __half* xr = in + (size_t)row*DIMM;
    float ls = 0.f;
    for (int c = tid; c < DIMM; c += 256) { float v = __half2float(xr[c]); buf[c] = v; ls += v*v; }
    red[tid] = ls; __syncthreads();
    for (int s2 = 128; s2 > 0; s2 >>= 1) { if (tid < s2) red[tid] += red[tid+s2]; __syncthreads(); }
    if (tid == 0) s_inv = rsqrtf(red[0]*(1.f/DIMM) + EPSF);
    __syncthreads();
    float inv = s_inv * oscale;
    if (do_rope) {
        for (int p = tid; p < DIMM/2; p += 256) {
            int hh = p >> 6, i = p & 63;
            float vr = buf[2*p]   * w[2*p]   * inv;
            float vi = buf[2*p+1] * w[2*p+1] * inv;
            float c = g_cos[s*64 + i], sn = g_sin[s*64 + i];
            size_t base = ((size_t)(b*HEADS + hh)*L + s) * HD;
            outT[base + 2*i]   = __float2half(vr*c - vi*sn);
            outT[base + 2*i+1] = __float2half(vr*sn + vi*c);
        }
    } else {
        for (int d = tid; d < DIMM; d += 256) {
            int hh = d >> 7, hd = d & 127;
            outT[((size_t)(b*HEADS + hh)*L + s)*HD + hd] = __float2half(buf[d]*inv*w[d]);
        }
    }
}

// ---------------- fp16 tensor-core GEMM v4 ----------------
// C[M,N] = A[M,K] @ W[K,N]. CTA 128x256x32, 8 warps (2x4, 64x64 each),
// 3-stage cp.async ring, ldmatrix / ldmatrix.trans fragments.
#define GLDH   40                       // A smem row halves (80B)
#define BLDH4  264                      // B smem row halves (528B; 528%128=16 -> conflict-free)
#define V4_A   (128*GLDH)               // 5120 halves
#define V4_B   (32*BLDH4)               // 8448 halves
#define V4_STG (V4_A + V4_B)            // 13568 halves = 27136 B
#define V4_SMEM (3*V4_STG*2)            // 81408 B
template<int EPI, typename OT>
__global__ __launch_bounds__(256, 1)
void k_gemm4(const __half* __restrict__ A, const __half* __restrict__ Bw,
             const float* __restrict__ bias, const float* __restrict__ res,
             const float* __restrict__ gate, OT* __restrict__ C,
             int M, int N, int K) {
    extern __shared__ __half sm[];
    int tid = threadIdx.x;
    int w = tid >> 5, lane = tid & 31;
    int bm = blockIdx.y << 7, bn = blockIdx.x << 8;
    const __half* Ab = A + (size_t)bm*K;

    int wm = (w >> 2)*64, wn = (w & 3)*64;
    int r = lane >> 2, cc = lane & 3;
    int mat = lane >> 3, lr = lane & 7;
    int lrow = (lane & 7) + ((lane >> 3) & 1)*8;   // B ldsm.trans lane mapping
    int lcol = (lane >> 4)*8;

    unsigned aoff[4], boff[4];
#pragma unroll
    for (int mi = 0; mi < 4; mi++)
        aoff[mi] = ((wm + mi*16 + ((mat & 1) << 3) + lr)*GLDH + ((mat >> 1) << 3)) * 2;
#pragma unroll
    for (int nj = 0; nj < 4; nj++)
        boff[nj] = (unsigned)((lrow*BLDH4 + wn + nj*16 + lcol) * 2);

    float acc[4][8][4];
#pragma unroll
    for (int i = 0; i < 4; i++)
#pragma unroll
        for (int j = 0; j < 8; j++)
#pragma unroll
            for (int t = 0; t < 4; t++) acc[i][j][t] = 0.f;

    auto stage = [&](int s, int kt) {
        __half* As = sm + s*V4_STG;
        __half* Bs = As + V4_A;
        int k0 = kt*32;
        // A: 512 chunks (128 rows x 4 segs of 8h)
#pragma unroll
        for (int i2 = 0; i2 < 2; i2++) {
            int ch = tid + i2*256;                 // 0..511
            int arow = ch >> 2, asg = ch & 3;
            cp16(&As[arow*GLDH + asg*8], Ab + (size_t)arow*K + k0 + asg*8);
        }
        // B: 1024 chunks (32 rows x 32 segs of 8h)
#pragma unroll
        for (int i2 = 0; i2 < 4; i2++) {
            int ch = tid + i2*256;                 // 0..1023
            int brow = ch >> 5, bsg = ch & 31;
            cp16(&Bs[brow*BLDH4 + bsg*8], Bw + (size_t)(k0 + brow)*N + bn + bsg*8);
        }
        cp_commit();
    };

    int nk = K >> 5;
    stage(0, 0); stage(1, 1);
    for (int kt = 0; kt < nk; kt++) {
        cp_wait1();
        __syncthreads();
        if (kt + 2 < nk) stage((kt+2) % 3, kt+2);
        else             cp_commit();
        int st = kt % 3;
        unsigned abase = (unsigned)__cvta_generic_to_shared(sm + st*V4_STG);
        unsigned bbase = abase + V4_A*2;
#pragma unroll
        for (int ks = 0; ks < 2; ks++) {
            unsigned af[4][4], bf[4][4];
#pragma unroll
            for (int mi = 0; mi < 4; mi++) ldsm4(af[mi], abase + aoff[mi] + ks*32);
#pragma unroll
            for (int nj = 0; nj < 4; nj++)
                ldsm4t(bf[nj][0], bf[nj][1], bf[nj][2], bf[nj][3],
                       bbase + boff[nj] + (unsigned)(ks*16*BLDH4*2));
#pragma unroll
            for (int mi = 0; mi < 4; mi++)
#pragma unroll
                for (int nj = 0; nj < 4; nj++) {
                    mma16816(acc[mi][2*nj],     af[mi], &bf[nj][0]);
                    mma16816(acc[mi][2*nj + 1], af[mi], &bf[nj][2]);
                }
        }
        __syncthreads();
    }

    // epilogue
#pragma unroll
    for (int mi = 0; mi < 4; mi++) {
        int row0 = bm + wm + mi*16 + r;
#pragma unroll
        for (int nj = 0; nj < 8; nj++) {
            int col0 = bn + wn + nj*8 + 2*cc;
#pragma unroll
            for (int t = 0; t < 4; t++) {
                int rr  = row0 + ((t >> 1) ? 8 : 0);
                int col = col0 + (t & 1);
                float v = acc[mi][nj][t] + bias[col];
                if (EPI == 1) {
                    float u = v;
                    float z = 0.7978845608028654f*(u + 0.044715f*u*u*u);
                    v = __fdividef(u, 1.f + __expf(-2.f*z));   // u * sigmoid(2z) == gelu_tanh
                }
                if (EPI == 2) v += res[(size_t)rr*N + col];
                if (EPI == 3) v = res[(size_t)rr*N + col] + v * gate[(rr >> 11)*EMSTR + col];
                stv(&C[(size_t)rr*N + col], v);
            }
        }
    }
}

// ---------------- fp16 flash attention (unchanged) ----------------
#define AT_LDS 136
#define KVSZ   (64*AT_LDS)
#define ATTN_H_SMEM (4*KVSZ*2)
__global__ __launch_bounds__(128)
void k_attn_h(const __half* __restrict__ qt, const __half* __restrict__ kt,
              const __half* __restrict__ vh, __half* __restrict__ y, int Lk) {
    extern __shared__ __half smh[];
    __half* Kb = smh;
    __half* Vb = smh + 2*KVSZ;

    int tid = threadIdx.x;
    int w = tid >> 5, lane = tid & 31;
    int r = lane >> 2, cc = lane & 3;
    int qtile = blockIdx.x, hh = blockIdx.y, b = blockIdx.z;

    const __half* qb = qt + ((size_t)(b*HEADS + hh)*SS + qtile*64) * HD;
    const __half* kb = kt + (size_t)(b*HEADS + hh)*Lk*HD;
    const __half* vb = vh + (size_t)b*Lk*DIMM + hh*HD;

    auto stage_kv = [&](int st, int t2) {
        __half* Kd = Kb + st*KVSZ;
        __half* Vd = Vb + st*KVSZ;
#pragma unroll
        for (int i2 = 0; i2 < 8; i2++) {
            int ch = tid + i2*128;
            int row = ch >> 4, sg = ch & 15;
            cp16(&Kd[row*AT_LDS + sg*8], kb + (size_t)(t2*64 + row)*HD + sg*8);
            cp16(&Vd[row*AT_LDS + sg*8], vb + (size_t)(t2*64 + row)*DIMM + sg*8);
        }
        cp_commit();
    };

    {
        __half* Qd = Kb + KVSZ;
#pragma unroll
        for (int i2 = 0; i2 < 8; i2++) {
            int ch = tid + i2*128;
            int row = ch >> 4, sg = ch & 15;
            cp16(&Qd[row*AT_LDS + sg*8], qb + (size_t)row*HD + sg*8);
        }
        stage_kv(0, 0);
    }
    cp_wait0();
    __syncthreads();

    unsigned afrq[8][4];
    {
        const __half* Qs = Kb + KVSZ;
#pragma unroll
        for (int kc = 0; kc < 8; kc++) {
            int row = w*16 + r, col = kc*16 + 2*cc;
            afrq[kc][0] = *(const unsigned*)&Qs[row*AT_LDS + col];
            afrq[kc][1] = *(const unsigned*)&Qs[(row+8)*AT_LDS + col];
            afrq[kc][2] = *(const unsigned*)&Qs[row*AT_LDS + col + 8];
            afrq[kc][3] = *(const unsigned*)&Qs[(row+8)*AT_LDS + col + 8];
        }
    }

    float acc[16][4];
#pragma unroll
    for (int i = 0; i < 16; i++)
#pragma unroll
        for (int t = 0; t < 4; t++) acc[i][t] = 0.f;
    float m0 = -1e30f, m1 = -1e30f, l0 = 0.f, l1 = 0.f;

    int ntiles = Lk >> 6;
    for (int t2 = 0; t2 < ntiles; t2++) {
        __syncthreads();
        if (t2 + 1 < ntiles) { stage_kv((t2+1) & 1, t2+1); cp_wait1(); }
        else                 { cp_wait0(); }
        __syncthreads();
        const __half* Ks = Kb + (t2&1)*KVSZ;
        const __half* Vs = Vb + (t2&1)*KVSZ;

        float sacc[8][4];
#pragma unroll
        for (int nb = 0; nb < 8; nb++)
#pragma unroll
            for (int t = 0; t < 4; t++) sacc[nb][t] = 0.f;
#pragma unroll
        for (int kc = 0; kc < 8; kc++) {
            unsigned bfr[8][2];
            int col = kc*16 + 2*cc;
#pragma unroll
            for (int nb = 0; nb < 8; nb++) {
                int krow = nb*8 + r;
                bfr[nb][0] = *(const unsigned*)&Ks[krow*AT_LDS + col];
                bfr[nb][1] = *(const unsigned*)&Ks[krow*AT_LDS + col + 8];
            }
#pragma unroll
            for (int nb = 0; nb < 8; nb++) mma16816(sacc[nb], afrq[kc], bfr[nb]);
        }

        float mx0 = -1e30f, mx1 = -1e30f;
#pragma unroll
        for (int nb = 0; nb < 8; nb++) {
            mx0 = fmaxf(mx0, fmaxf(sacc[nb][0], sacc[nb][1]));
            mx1 = fmaxf(mx1, fmaxf(sacc[nb][2], sacc[nb][3]));
        }
        mx0 = fmaxf(mx0, __shfl_xor_sync(0xffffffffu, mx0, 1));
        mx0 = fmaxf(mx0, __shfl_xor_sync(0xffffffffu, mx0, 2));
        mx1 = fmaxf(mx1, __shfl_xor_sync(0xffffffffu, mx1, 1));
        mx1 = fmaxf(mx1, __shfl_xor_sync(0xffffffffu, mx1, 2));
        float mn0 = fmaxf(m0, mx0), mn1 = fmaxf(m1, mx1);
        float esc0 = __expf(m0 - mn0), esc1 = __expf(m1 - mn1);
        m0 = mn0; m1 = mn1;
        float ls0 = 0.f, ls1 = 0.f;
#pragma unroll
        for (int nb = 0; nb < 8; nb++) {
            sacc[nb][0] = __expf(sacc[nb][0] - mn0); ls0 += sacc[nb][0];
            sacc[nb][1] = __expf(sacc[nb][1] - mn0); ls0 += sacc[nb][1];
            sacc[nb][2] = __expf(sacc[nb][2] - mn1); ls1 += sacc[nb][2];
            sacc[nb][3] = __expf(sacc[nb][3] - mn1); ls1 += sacc[nb][3];
        }
        ls0 += __shfl_xor_sync(0xffffffffu, ls0, 1);
        ls0 += __shfl_xor_sync(0xffffffffu, ls0, 2);
        ls1 += __shfl_xor_sync(0xffffffffu, ls1, 1);
        ls1 += __shfl_xor_sync(0xffffffffu, ls1, 2);
        l0 = l0*esc0 + ls0;
        l1 = l1*esc1 + ls1;

        unsigned pf[4][4];
#pragma unroll
        for (int kc = 0; kc < 4; kc++) {
            pf[kc][0] = packh2(sacc[2*kc][0],   sacc[2*kc][1]);
            pf[kc][1] = packh2(sacc[2*kc][2],   sacc[2*kc][3]);
            pf[kc][2] = packh2(sacc[2*kc+1][0], sacc[2*kc+1][1]);
            pf[kc][3] = packh2(sacc[2*kc+1][2], sacc[2*kc+1][3]);
        }
#pragma unroll
        for (int nb = 0; nb < 16; nb++) {
            acc[nb][0] *= esc0; acc[nb][1] *= esc0;
            acc[nb][2] *= esc1; acc[nb][3] *= esc1;
        }

        unsigned vbase = (unsigned)__cvta_generic_to_shared(Vs);
        int lrow = (lane & 7) + ((lane >> 3) & 1)*8;
        int lcol = (lane >> 4)*8;
#pragma unroll
        for (int np = 0; np < 8; np++) {
#pragma unroll
            for (int kc = 0; kc < 4; kc++) {
                unsigned r0, r1, r2, r3;
                unsigned addr = vbase + (unsigned)(((kc*16 + lrow)*AT_LDS + np*16 + lcol)*2);
                ldsm4t(r0, r1, r2, r3, addr);
                unsigned b0[2] = {r0, r1};
                unsigned b1[2] = {r2, r3};
                mma16816(acc[np*2],     pf[kc], b0);
                mma16816(acc[np*2 + 1], pf[kc], b1);
            }
        }
    }

    float inv0 = 1.f/l0, inv1 = 1.f/l1;
    int row0 = qtile*64 + w*16 + r;
    __half* yb = y + (size_t)b*SS*DIMM + hh*HD;
#pragma unroll
    for (int nb = 0; nb < 16; nb++) {
        int col = nb*8 + 2*cc;
        __half2 h0 = __floats2half2_rn(acc[nb][0]*inv0, acc[nb][1]*inv0);
        __half2 h1 = __floats2half2_rn(acc[nb][2]*inv1, acc[nb][3]*inv1);
        *(__half2*)&yb[(size_t)row0*DIMM + col]     = h0;
        *(__half2*)&yb[(size_t)(row0+8)*DIMM + col] = h1;
    }
}

// ---------------- host ----------------
extern "C" void kernel_launch(void* const* d_in, const int* in_sizes, int n_in,
                              void* d_out, int out_size) {
    const float* x       = (const float*)d_in[0];
    const float* e       = (const float*)d_in[1];
    const float* context = (const float*)d_in[2];
    const float* fcos    = (const float*)d_in[3];
    const float* fsin    = (const float*)d_in[4];
    const float* modu    = (const float*)d_in[5];
    const float* sa_wq = (const float*)d_in[6];  const float* sa_bq = (const float*)d_in[7];
    const float* sa_wk = (const float*)d_in[8];  const float* sa_bk = (const float*)d_in[9];
    const float* sa_wv = (const float*)d_in[10]; const float* sa_bv = (const float*)d_in[11];
    const float* sa_wo = (const float*)d_in[12]; const float* sa_bo = (const float*)d_in[13];
    const float* sa_nq = (const float*)d_in[14]; const float* sa_nk = (const float*)d_in[15];
    const float* ca_wq = (const float*)d_in[16]; const float* ca_bq = (const float*)d_in[17];
    const float* ca_wk = (const float*)d_in[18]; const float* ca_bk = (const float*)d_in[19];
    const float* ca_wv = (const float*)d_in[20]; const float* ca_bv = (const float*)d_in[21];
    const float* ca_wo = (const float*)d_in[22]; const float* ca_bo = (const float*)d_in[23];
    const float* ca_nq = (const float*)d_in[24]; const float* ca_nk = (const float*)d_in[25];
    const float* n3_w  = (const float*)d_in[26]; const float* n3_b  = (const float*)d_in[27];
    const float* w1    = (const float*)d_in[28]; const float* b1    = (const float*)d_in[29];
    const float* w2    = (const float*)d_in[30]; const float* b2    = (const float*)d_in[31];
    float* out = (float*)d_out;

    float *em, *cb, *sb2, *xb;
    __half *tmph, *qh, *kh, *vhp, *xn, *y, *h, *ctxh, *wt;
    cudaGetSymbolAddress((void**)&em,   g_em);
    cudaGetSymbolAddress((void**)&cb,   g_cos);
    cudaGetSymbolAddress((void**)&sb2,  g_sin);
    cudaGetSymbolAddress((void**)&xb,   g_x);
    cudaGetSymbolAddress((void**)&tmph, g_tmp);
    cudaGetSymbolAddress((void**)&qh,   g_qh);
    cudaGetSymbolAddress((void**)&kh,   g_kh);
    cudaGetSymbolAddress((void**)&vhp,  g_vh);
    cudaGetSymbolAddress((void**)&xn,   g_xn);
    cudaGetSymbolAddress((void**)&y,    g_y);
    cudaGetSymbolAddress((void**)&h,    g_h);
    cudaGetSymbolAddress((void**)&ctxh, g_ctx);
    cudaGetSymbolAddress((void**)&wt,   g_wt);

    cudaFuncSetAttribute(k_attn_h, cudaFuncAttributeMaxDynamicSharedMemorySize, ATTN_H_SMEM);
    cudaFuncSetAttribute(k_gemm4<0,float>,  cudaFuncAttributeMaxDynamicSharedMemorySize, V4_SMEM);
    cudaFuncSetAttribute(k_gemm4<0,__half>, cudaFuncAttributeMaxDynamicSharedMemorySize, V4_SMEM);
    cudaFuncSetAttribute(k_gemm4<1,__half>, cudaFuncAttributeMaxDynamicSharedMemorySize, V4_SMEM);
    cudaFuncSetAttribute(k_gemm4<2,float>,  cudaFuncAttributeMaxDynamicSharedMemorySize, V4_SMEM);
    cudaFuncSetAttribute(k_gemm4<3,float>,  cudaFuncAttributeMaxDynamicSharedMemorySize, V4_SMEM);

    const float QSC = 0.08838834764831845f;  // 1/sqrt(128)

    dim3 blk(256);
    dim3 gP(DIMM/256, M1/128);       // (8, 32)
    dim3 gC(DIMM/256, MC/128);       // (8, 8)
    dim3 gF1(FFN/256, M1/128);       // (32, 32)
    dim3 gF2(DIMM/256, M1/128);      // (8, 32)
    dim3 gA(SS/64, HEADS, BB);

    const int NW = DIMM*DIMM;        // 4M elems
    const int NF = DIMM*FFN;         // 16M elems

    // ---- pre-pass: straight fp32->fp16 converts ----
    k_h8<<<NW/8/256, blk>>>(sa_wq, wt + WT_Q,  NW);
    k_h8<<<NW/8/256, blk>>>(sa_wk, wt + WT_K,  NW);
    k_h8<<<NW/8/256, blk>>>(sa_wv, wt + WT_V,  NW);
    k_h8<<<NW/8/256, blk>>>(sa_wo, wt + WT_O,  NW);
    k_h8<<<NW/8/256, blk>>>(ca_wq, wt + WT_CQ, NW);
    k_h8<<<NW/8/256, blk>>>(ca_wk, wt + WT_CK, NW);
    k_h8<<<NW/8/256, blk>>>(ca_wv, wt + WT_CV, NW);
    k_h8<<<NW/8/256, blk>>>(ca_wo, wt + WT_CO, NW);
    k_h8<<<NF/8/256, blk>>>(w1,    wt + WT_F1, NF);
    k_h8<<<NF/8/256, blk>>>(w2,    wt + WT_F2, NF);
    k_h8<<<(MC*DIMM)/8/256, blk>>>(context, ctxh, MC*DIMM);
    k_embed<<<(BB*6*DIMM + 255)/256, blk>>>(modu, e, em);
    k_ropetab<<<(SS*64 + 255)/256, blk>>>(fcos, fsin, cb, sb2);

    // ---- self attention ----
    k_ln<<<M1, blk>>>(x, em + 1*DIMM, em + 0*DIMM, 1, xn);
    k_gemm4<0,__half><<<gP, blk, V4_SMEM>>>(xn, wt + WT_Q, sa_bq, nullptr, nullptr, tmph, M1, DIMM, DIMM);
    k_rms_t<<<M1, blk>>>(tmph, sa_nq, qh, SS, 1, QSC);
    k_gemm4<0,__half><<<gP, blk, V4_SMEM>>>(xn, wt + WT_K, sa_bk, nullptr, nullptr, tmph, M1, DIMM, DIMM);
    k_rms_t<<<M1, blk>>>(tmph, sa_nk, kh, SS, 1, 1.f);
    k_gemm4<0,__half><<<gP, blk, V4_SMEM>>>(xn, wt + WT_V, sa_bv, nullptr, nullptr, vhp, M1, DIMM, DIMM);
    k_attn_h<<<gA, 128, ATTN_H_SMEM>>>(qh, kh, vhp, y, SS);
    k_gemm4<3,float><<<gP, blk, V4_SMEM>>>(y, wt + WT_O, sa_bo, x, em + 2*DIMM, xb, M1, DIMM, DIMM);

    // ---- cross attention ----
    k_ln<<<M1, blk>>>(xb, n3_w, n3_b, 0, xn);
    k_gemm4<0,__half><<<gP, blk, V4_SMEM>>>(xn, wt + WT_CQ, ca_bq, nullptr, nullptr, tmph, M1, DIMM, DIMM);
    k_rms_t<<<M1, blk>>>(tmph, ca_nq, qh, SS, 0, QSC);
    k_gemm4<0,__half><<<gC, blk, V4_SMEM>>>(ctxh, wt + WT_CK, ca_bk, nullptr, nullptr, tmph, MC, DIMM, DIMM);
    k_rms_t<<<MC, blk>>>(tmph, ca_nk, kh, CTX, 0, 1.f);
    k_gemm4<0,__half><<<gC, blk, V4_SMEM>>>(ctxh, wt + WT_CV, ca_bv, nullptr, nullptr, vhp, MC, DIMM, DIMM);
    k_attn_h<<<gA, 128, ATTN_H_SMEM>>>(qh, kh, vhp, y, CTX);
    k_gemm4<2,float><<<gP, blk, V4_SMEM>>>(y, wt + WT_CO, ca_bo, xb, nullptr, xb, M1, DIMM, DIMM);

    // ---- FFN ----
    k_ln<<<M1, blk>>>(xb, em + 4*DIMM, em + 3*DIMM, 1, xn);
    k_gemm4<1,__half><<<gF1, blk, V4_SMEM>>>(xn, wt + WT_F1, b1, nullptr, nullptr, h, M1, FFN, DIMM);
    k_gemm4<3,float><<<gF2, blk, V4_SMEM>>>(h, wt + WT_F2, b2, xb, em + 5*DIMM, out, M1, DIMM, FFN);
}

// round 11
// speedup vs baseline: 1.2733x; 1.2733x over previous
#include <cuda_runtime.h>
#include <cuda_fp16.h>
#include <math.h>
#include <stddef.h>
#include <stdint.h>

// ---------------- problem constants ----------------
#define BB     2
#define SS     2048
#define DIMM   2048
#define HEADS  16
#define HD     128
#define FFN    8192
#define CTX    512
#define M1     (BB*SS)
#define MC     (BB*CTX)
#define EMSTR  (6*DIMM)
#define EPSF   1e-6f

// ---------------- device scratch ----------------
__device__ float g_em [BB*6*DIMM];
__device__ float g_cos[SS*(HD/2)];
__device__ float g_sin[SS*(HD/2)];
__device__ float g_x  [M1*DIMM];
__device__ __align__(128) __half g_tmp[M1*DIMM];     // pre-norm q/k (fp16)
__device__ __align__(128) __half g_qh [BB*HEADS*SS*HD];
__device__ __align__(128) __half g_kh [BB*HEADS*SS*HD];
__device__ __align__(128) __half g_vh [M1*DIMM];
__device__ __align__(128) __half g_xn [M1*DIMM];
__device__ __align__(128) __half g_y  [M1*DIMM];
__device__ __align__(128) __half g_h  [(size_t)M1*FFN];
__device__ __align__(128) __half g_ctx[MC*DIMM];
__device__ __align__(128) __half g_wt [64*1024*1024];

#define WT_Q   ((size_t)0)
#define WT_K   ((size_t)4*1024*1024)
#define WT_V   ((size_t)8*1024*1024)
#define WT_O   ((size_t)12*1024*1024)
#define WT_CQ  ((size_t)16*1024*1024)
#define WT_CK  ((size_t)20*1024*1024)
#define WT_CV  ((size_t)24*1024*1024)
#define WT_CO  ((size_t)28*1024*1024)
#define WT_F1  ((size_t)32*1024*1024)
#define WT_F2  ((size_t)48*1024*1024)

// ---------------- helpers ----------------
__device__ __forceinline__ void cp16(void* smem, const void* g) {
    unsigned s = (unsigned)__cvta_generic_to_shared(smem);
    asm volatile("cp.async.cg.shared.global [%0], [%1], 16;\n" :: "r"(s), "l"(g));
}
__device__ __forceinline__ void cp_commit() { asm volatile("cp.async.commit_group;\n"); }
__device__ __forceinline__ void cp_wait0()  { asm volatile("cp.async.wait_group 0;\n"); }
__device__ __forceinline__ void cp_wait1()  { asm volatile("cp.async.wait_group 1;\n"); }
__device__ __forceinline__ void cp_wait2()  { asm volatile("cp.async.wait_group 2;\n"); }

__device__ __forceinline__ void mma16816(float* d, const unsigned* a, const unsigned* b) {
    asm volatile(
        "mma.sync.aligned.m16n8k16.row.col.f32.f16.f16.f32 "
        "{%0,%1,%2,%3}, {%4,%5,%6,%7}, {%8,%9}, {%0,%1,%2,%3};\n"
        : "+f"(d[0]), "+f"(d[1]), "+f"(d[2]), "+f"(d[3])
        : "r"(a[0]), "r"(a[1]), "r"(a[2]), "r"(a[3]), "r"(b[0]), "r"(b[1]));
}
__device__ __forceinline__ void ldsm4(unsigned* r, unsigned saddr) {
    asm volatile("ldmatrix.sync.aligned.m8n8.x4.shared.b16 {%0,%1,%2,%3}, [%4];\n"
                 : "=r"(r[0]), "=r"(r[1]), "=r"(r[2]), "=r"(r[3]) : "r"(saddr));
}
__device__ __forceinline__ void ldsm4t(unsigned& r0, unsigned& r1, unsigned& r2, unsigned& r3,
                                       unsigned saddr) {
    asm volatile("ldmatrix.sync.aligned.m8n8.x4.trans.shared.b16 {%0,%1,%2,%3}, [%4];\n"
                 : "=r"(r0), "=r"(r1), "=r"(r2), "=r"(r3) : "r"(saddr));
}
__device__ __forceinline__ unsigned packh2(float a, float b) {
    __half2 h = __floats2half2_rn(a, b);
    return *reinterpret_cast<unsigned*>(&h);
}

template<typename OT> __device__ __forceinline__ void stv(OT* p, float v);
template<> __device__ __forceinline__ void stv<float >(float*  p, float v) { *p = v; }
template<> __device__ __forceinline__ void stv<__half>(__half* p, float v) { *p = __float2half(v); }

// ---------------- small kernels ----------------
__global__ void k_embed(const float* __restrict__ mo, const float* __restrict__ e,
                        float* __restrict__ em) {
    int i = blockIdx.x*256 + threadIdx.x;
    if (i < BB*6*DIMM) em[i] = mo[i % EMSTR] + e[i];
}

__global__ void k_ropetab(const float* __restrict__ fc, const float* __restrict__ fs,
                          float* __restrict__ cb, float* __restrict__ sb) {
    int i = blockIdx.x*256 + threadIdx.x;
    if (i >= SS*64) return;
    int s = i >> 6, d = i & 63;
    int f = s >> 8, h = (s >> 4) & 15, w = s & 15;
    int row = (d < 22) ? f : ((d < 43) ? h : w);
    cb[i] = fc[row*64 + d];
    sb[i] = fs[row*64 + d];
}

// vectorized fp32 -> fp16 convert (8 elems/thread)
__global__ void k_h8(const float* __restrict__ in, __half* __restrict__ out, int n) {
    int i = (blockIdx.x*256 + threadIdx.x)*8;
    if (i < n) {
        float4 a = *(const float4*)(in + i);
        float4 b = *(const float4*)(in + i + 4);
        __half2 h0 = __floats2half2_rn(a.x, a.y), h1 = __floats2half2_rn(a.z, a.w);
        __half2 h2 = __floats2half2_rn(b.x, b.y), h3 = __floats2half2_rn(b.z, b.w);
        uint4 u;
        u.x = *(unsigned*)&h0; u.y = *(unsigned*)&h1;
        u.z = *(unsigned*)&h2; u.w = *(unsigned*)&h3;
        *(uint4*)(out + i) = u;
    }
}

__global__ void k_ln(const float* __restrict__ x, const float* __restrict__ scv,
                     const float* __restrict__ shv, int em_mode, __half* __restrict__ out) {
    __shared__ float buf[DIMM];
    __shared__ float red[256];
    __shared__ float s_m, s_inv;
    int row = blockIdx.x, tid = threadIdx.x;
    const float* xr = x + (size_t)row*DIMM;
    float ls = 0.f;
    for (int c = tid; c < DIMM; c += 256) { float v = xr[c]; buf[c] = v; ls += v; }
    red[tid] = ls; __syncthreads();
    for (int s2 = 128; s2 > 0; s2 >>= 1) { if (tid < s2) red[tid] += red[tid+s2]; __syncthreads(); }
    if (tid == 0) s_m = red[0] * (1.f/DIMM);
    __syncthreads();
    float m = s_m, lv = 0.f;
    for (int c = tid; c < DIMM; c += 256) { float d = buf[c]-m; lv += d*d; }
    red[tid] = lv; __syncthreads();
    for (int s2 = 128; s2 > 0; s2 >>= 1) { if (tid < s2) red[tid] += red[tid+s2]; __syncthreads(); }
    if (tid == 0) s_inv = rsqrtf(red[0]*(1.f/DIMM) + EPSF);
    __syncthreads();
    float inv = s_inv;
    int bo = (row >> 11) * EMSTR;
    __half* orow = out + (size_t)row*DIMM;
    for (int c = tid; c < DIMM; c += 256) {
        float sc, sh;
        if (em_mode) { sc = 1.f + scv[bo+c]; sh = shv[bo+c]; }
        else         { sc = scv[c];          sh = shv[c];    }
        orow[c] = __float2half((buf[c]-m)*inv*sc + sh);
    }
}

// RMS norm (fp16 input) + optional RoPE + transpose to [B,H,L,HD]
__global__ void k_rms_t(const __half* __restrict__ in, const float* __restrict__ w,
                        __half* __restrict__ outT, int L, int do_rope, float oscale) {
    __shared__ float buf[DIMM];
    __shared__ float red[256];
    __shared__ float s_inv;
    int row = blockIdx.x, tid = threadIdx.x;
    int b = row / L, s = row % L;
    const __half* xr = in + (size_t)row*DIMM;
    float ls = 0.f;
    for (int c = tid; c < DIMM; c += 256) { float v = __half2float(xr[c]); buf[c] = v; ls += v*v; }
    red[tid] = ls; __syncthreads();
    for (int s2 = 128; s2 > 0; s2 >>= 1) { if (tid < s2) red[tid] += red[tid+s2]; __syncthreads(); }
    if (tid == 0) s_inv = rsqrtf(red[0]*(1.f/DIMM) + EPSF);
    __syncthreads();
    float inv = s_inv * oscale;
    if (do_rope) {
        for (int p = tid; p < DIMM/2; p += 256) {
            int hh = p >> 6, i = p & 63;
            float vr = buf[2*p]   * w[2*p]   * inv;
            float vi = buf[2*p+1] * w[2*p+1] * inv;
            float c = g_cos[s*64 + i], sn = g_sin[s*64 + i];
            size_t base = ((size_t)(b*HEADS + hh)*L + s) * HD;
            outT[base + 2*i]   = __float2half(vr*c - vi*sn);
            outT[base + 2*i+1] = __float2half(vr*sn + vi*c);
        }
    } else {
        for (int d = tid; d < DIMM; d += 256) {
            int hh = d >> 7, hd = d & 127;
            outT[((size_t)(b*HEADS + hh)*L + s)*HD + hd] = __float2half(buf[d]*inv*w[d]);
        }
    }
}

// ---------------- fp16 tensor-core GEMM v3 (R9, proven 2091) ----------------
#define GLDH   40                       // A smem row halves (80B)
#define BLDH   136                      // B smem row halves (272B)
#define V3_A   (128*GLDH)               // 5120 halves
#define V3_B   (32*BLDH)                // 4352 halves
#define V3_STG (V3_A + V3_B)            // 9472 halves = 18944 B
#define V3_SMEM (4*V3_STG*2)            // 75776 B
template<int EPI, typename OT>
__global__ __launch_bounds__(128, 2)
void k_gemm3(const __half* __restrict__ A, const __half* __restrict__ Bw,
             const float* __restrict__ bias, const float* __restrict__ res,
             const float* __restrict__ gate, OT* __restrict__ C,
             int M, int N, int K) {
    extern __shared__ __half sm[];
    int tid = threadIdx.x;
    int w = tid >> 5, lane = tid & 31;
    int bm = blockIdx.y << 7, bn = blockIdx.x << 7;
    const __half* Ab = A + (size_t)bm*K;

    int wm = (w >> 1)*64, wn = (w & 1)*64;
    int r = lane >> 2, cc = lane & 3;
    int mat = lane >> 3, lr = lane & 7;
    int lrow = (lane & 7) + ((lane >> 3) & 1)*8;   // B ldsm.trans lane mapping
    int lcol = (lane >> 4)*8;

    unsigned aoff[4], boff[4];
#pragma unroll
    for (int mi = 0; mi < 4; mi++)
        aoff[mi] = ((wm + mi*16 + ((mat & 1) << 3) + lr)*GLDH + ((mat >> 1) << 3)) * 2;
#pragma unroll
    for (int nj = 0; nj < 4; nj++)
        boff[nj] = (unsigned)((lrow*BLDH + wn + nj*16 + lcol) * 2);

    float acc[4][8][4];
#pragma unroll
    for (int i = 0; i < 4; i++)
#pragma unroll
        for (int j = 0; j < 8; j++)
#pragma unroll
            for (int t = 0; t < 4; t++) acc[i][j][t] = 0.f;

    auto stage = [&](int s, int kt) {
        __half* As = sm + s*V3_STG;
        __half* Bs = As + V3_A;
        int k0 = kt*32;
#pragma unroll
        for (int i2 = 0; i2 < 4; i2++) {
            int ch = tid + i2*128;                 // 0..511
            int arow = ch >> 2, asg = ch & 3;
            cp16(&As[arow*GLDH + asg*8], Ab + (size_t)arow*K + k0 + asg*8);
            int brow = ch >> 4, bsg = ch & 15;
            cp16(&Bs[brow*BLDH + bsg*8], Bw + (size_t)(k0 + brow)*N + bn + bsg*8);
        }
        cp_commit();
    };

    int nk = K >> 5;
    stage(0, 0); stage(1, 1); stage(2, 2);
    for (int kt = 0; kt < nk; kt++) {
        cp_wait2();
        __syncthreads();
        if (kt + 3 < nk) stage((kt+3) & 3, kt+3);
        else             cp_commit();
        int st = kt & 3;
        unsigned abase = (unsigned)__cvta_generic_to_shared(sm + st*V3_STG);
        unsigned bbase = abase + V3_A*2;
#pragma unroll
        for (int ks = 0; ks < 2; ks++) {
            unsigned af[4][4], bf[4][4];
#pragma unroll
            for (int mi = 0; mi < 4; mi++) ldsm4(af[mi], abase + aoff[mi] + ks*32);
#pragma unroll
            for (int nj = 0; nj < 4; nj++)
                ldsm4t(bf[nj][0], bf[nj][1], bf[nj][2], bf[nj][3],
                       bbase + boff[nj] + (unsigned)(ks*16*BLDH*2));
#pragma unroll
            for (int mi = 0; mi < 4; mi++)
#pragma unroll
                for (int nj = 0; nj < 4; nj++) {
                    mma16816(acc[mi][2*nj],     af[mi], &bf[nj][0]);
                    mma16816(acc[mi][2*nj + 1], af[mi], &bf[nj][2]);
                }
        }
        __syncthreads();
    }

    // epilogue
#pragma unroll
    for (int mi = 0; mi < 4; mi++) {
        int row0 = bm + wm + mi*16 + r;
#pragma unroll
        for (int nj = 0; nj < 8; nj++) {
            int col0 = bn + wn + nj*8 + 2*cc;
#pragma unroll
            for (int t = 0; t < 4; t++) {
                int rr  = row0 + ((t >> 1) ? 8 : 0);
                int col = col0 + (t & 1);
                float v = acc[mi][nj][t] + bias[col];
                if (EPI == 1) {
                    float u = v;
                    float z = 0.7978845608028654f*(u + 0.044715f*u*u*u);
                    v = __fdividef(u, 1.f + __expf(-2.f*z));   // u * sigmoid(2z) == gelu_tanh
                }
                if (EPI == 2) v += res[(size_t)rr*N + col];
                if (EPI == 3) v = res[(size_t)rr*N + col] + v * gate[(rr >> 11)*EMSTR + col];
                stv(&C[(size_t)rr*N + col], v);
            }
        }
    }
}

// ---------------- fp16 flash attention, 128-row Q tiles ----------------
// 256 threads, 8 warps x 16 query rows. KV traffic halved vs 64-row tiles.
#define AT_LDS 136
#define KVSZ   (64*AT_LDS)
#define QSZ    (128*AT_LDS)
#define ATTN_H_SMEM ((4*KVSZ + QSZ)*2)   // 104448 bytes
__global__ __launch_bounds__(256)
void k_attn_h(const __half* __restrict__ qt, const __half* __restrict__ kt,
              const __half* __restrict__ vh, __half* __restrict__ y, int Lk) {
    extern __shared__ __half smh[];
    __half* Kb = smh;                 // 2 * KVSZ
    __half* Vb = smh + 2*KVSZ;        // 2 * KVSZ
    __half* Qs = smh + 4*KVSZ;        // QSZ (persists)

    int tid = threadIdx.x;
    int w = tid >> 5, lane = tid & 31;
    int r = lane >> 2, cc = lane & 3;
    int qtile = blockIdx.x, hh = blockIdx.y, b = blockIdx.z;

    const __half* qb = qt + ((size_t)(b*HEADS + hh)*SS + qtile*128) * HD;
    const __half* kb = kt + (size_t)(b*HEADS + hh)*Lk*HD;
    const __half* vb = vh + (size_t)b*Lk*DIMM + hh*HD;

    // stage K+V tile: 64 rows x 128 halves = 1024 chunks each (256 threads)
    auto stage_kv = [&](int st, int t2) {
        __half* Kd = Kb + st*KVSZ;
        __half* Vd = Vb + st*KVSZ;
#pragma unroll
        for (int i2 = 0; i2 < 4; i2++) {
            int ch = tid + i2*256;
            int row = ch >> 4, sg = ch & 15;
            cp16(&Kd[row*AT_LDS + sg*8], kb + (size_t)(t2*64 + row)*HD + sg*8);
            cp16(&Vd[row*AT_LDS + sg*8], vb + (size_t)(t2*64 + row)*DIMM + sg*8);
        }
        cp_commit();
    };

    // initial: Q tile (128 rows = 2048 chunks) + KV tile0, one group
    {
#pragma unroll
        for (int i2 = 0; i2 < 8; i2++) {
            int ch = tid + i2*256;
            int row = ch >> 4, sg = ch & 15;
            cp16(&Qs[row*AT_LDS + sg*8], qb + (size_t)row*HD + sg*8);
        }
        stage_kv(0, 0);
    }
    cp_wait0();
    __syncthreads();

    // Q fragments (registers, warp w covers rows w*16..w*16+15)
    unsigned afrq[8][4];
#pragma unroll
    for (int kc = 0; kc < 8; kc++) {
        int row = w*16 + r, col = kc*16 + 2*cc;
        afrq[kc][0] = *(const unsigned*)&Qs[row*AT_LDS + col];
        afrq[kc][1] = *(const unsigned*)&Qs[(row+8)*AT_LDS + col];
        afrq[kc][2] = *(const unsigned*)&Qs[row*AT_LDS + col + 8];
        afrq[kc][3] = *(const unsigned*)&Qs[(row+8)*AT_LDS + col + 8];
    }

    float acc[16][4];
#pragma unroll
    for (int i = 0; i < 16; i++)
#pragma unroll
        for (int t = 0; t < 4; t++) acc[i][t] = 0.f;
    float m0 = -1e30f, m1 = -1e30f, l0 = 0.f, l1 = 0.f;

    int ntiles = Lk >> 6;
    for (int t2 = 0; t2 < ntiles; t2++) {
        __syncthreads();
        if (t2 + 1 < ntiles) { stage_kv((t2+1) & 1, t2+1); cp_wait1(); }
        else                 { cp_wait0(); }
        __syncthreads();
        const __half* Ks = Kb + (t2&1)*KVSZ;
        const __half* Vs = Vb + (t2&1)*KVSZ;

        // ---- S = Q K^T (16x64 per warp) ----
        float sacc[8][4];
#pragma unroll
        for (int nb = 0; nb < 8; nb++)
#pragma unroll
            for (int t = 0; t < 4; t++) sacc[nb][t] = 0.f;
#pragma unroll
        for (int kc = 0; kc < 8; kc++) {
            unsigned bfr[8][2];
            int col = kc*16 + 2*cc;
#pragma unroll
            for (int nb = 0; nb < 8; nb++) {
                int krow = nb*8 + r;
                bfr[nb][0] = *(const unsigned*)&Ks[krow*AT_LDS + col];
                bfr[nb][1] = *(const unsigned*)&Ks[krow*AT_LDS + col + 8];
            }
#pragma unroll
            for (int nb = 0; nb < 8; nb++) mma16816(sacc[nb], afrq[kc], bfr[nb]);
        }

        // ---- online softmax ----
        float mx0 = -1e30f, mx1 = -1e30f;
#pragma unroll
        for (int nb = 0; nb < 8; nb++) {
            mx0 = fmaxf(mx0, fmaxf(sacc[nb][0], sacc[nb][1]));
            mx1 = fmaxf(mx1, fmaxf(sacc[nb][2], sacc[nb][3]));
        }
        mx0 = fmaxf(mx0, __shfl_xor_sync(0xffffffffu, mx0, 1));
        mx0 = fmaxf(mx0, __shfl_xor_sync(0xffffffffu, mx0, 2));
        mx1 = fmaxf(mx1, __shfl_xor_sync(0xffffffffu, mx1, 1));
        mx1 = fmaxf(mx1, __shfl_xor_sync(0xffffffffu, mx1, 2));
        float mn0 = fmaxf(m0, mx0), mn1 = fmaxf(m1, mx1);
        float esc0 = __expf(m0 - mn0), esc1 = __expf(m1 - mn1);
        m0 = mn0; m1 = mn1;
        float ls0 = 0.f, ls1 = 0.f;
#pragma unroll
        for (int nb = 0; nb < 8; nb++) {
            sacc[nb][0] = __expf(sacc[nb][0] - mn0); ls0 += sacc[nb][0];
            sacc[nb][1] = __expf(sacc[nb][1] - mn0); ls0 += sacc[nb][1];
            sacc[nb][2] = __expf(sacc[nb][2] - mn1); ls1 += sacc[nb][2];
            sacc[nb][3] = __expf(sacc[nb][3] - mn1); ls1 += sacc[nb][3];
        }
        ls0 += __shfl_xor_sync(0xffffffffu, ls0, 1);
        ls0 += __shfl_xor_sync(0xffffffffu, ls0, 2);
        ls1 += __shfl_xor_sync(0xffffffffu, ls1, 1);
        ls1 += __shfl_xor_sync(0xffffffffu, ls1, 2);
        l0 = l0*esc0 + ls0;
        l1 = l1*esc1 + ls1;

        unsigned pf[4][4];
#pragma unroll
        for (int kc = 0; kc < 4; kc++) {
            pf[kc][0] = packh2(sacc[2*kc][0],   sacc[2*kc][1]);
            pf[kc][1] = packh2(sacc[2*kc][2],   sacc[2*kc][3]);
            pf[kc][2] = packh2(sacc[2*kc+1][0], sacc[2*kc+1][1]);
            pf[kc][3] = packh2(sacc[2*kc+1][2], sacc[2*kc+1][3]);
        }
#pragma unroll
        for (int nb = 0; nb < 16; nb++) {
            acc[nb][0] *= esc0; acc[nb][1] *= esc0;
            acc[nb][2] *= esc1; acc[nb][3] *= esc1;
        }

        // ---- O += P V ----
        unsigned vbase = (unsigned)__cvta_generic_to_shared(Vs);
        int lrow = (lane & 7) + ((lane >> 3) & 1)*8;
        int lcol = (lane >> 4)*8;
#pragma unroll
        for (int np = 0; np < 8; np++) {
#pragma unroll
            for (int kc = 0; kc < 4; kc++) {
                unsigned r0, r1, r2, r3;
                unsigned addr = vbase + (unsigned)(((kc*16 + lrow)*AT_LDS + np*16 + lcol)*2);
                ldsm4t(r0, r1, r2, r3, addr);
                unsigned b0[2] = {r0, r1};
                unsigned b1[2] = {r2, r3};
                mma16816(acc[np*2],     pf[kc], b0);
                mma16816(acc[np*2 + 1], pf[kc], b1);
            }
        }
    }

    // ---- epilogue ----
    float inv0 = 1.f/l0, inv1 = 1.f/l1;
    int row0 = qtile*128 + w*16 + r;
    __half* yb = y + (size_t)b*SS*DIMM + hh*HD;
#pragma unroll
    for (int nb = 0; nb < 16; nb++) {
        int col = nb*8 + 2*cc;
        __half2 h0 = __floats2half2_rn(acc[nb][0]*inv0, acc[nb][1]*inv0);
        __half2 h1 = __floats2half2_rn(acc[nb][2]*inv1, acc[nb][3]*inv1);
        *(__half2*)&yb[(size_t)row0*DIMM + col]     = h0;
        *(__half2*)&yb[(size_t)(row0+8)*DIMM + col] = h1;
    }
}

// ---------------- host ----------------
extern "C" void kernel_launch(void* const* d_in, const int* in_sizes, int n_in,
                              void* d_out, int out_size) {
    const float* x       = (const float*)d_in[0];
    const float* e       = (const float*)d_in[1];
    const float* context = (const float*)d_in[2];
    const float* fcos    = (const float*)d_in[3];
    const float* fsin    = (const float*)d_in[4];
    const float* modu    = (const float*)d_in[5];
    const float* sa_wq = (const float*)d_in[6];  const float* sa_bq = (const float*)d_in[7];
    const float* sa_wk = (const float*)d_in[8];  const float* sa_bk = (const float*)d_in[9];
    const float* sa_wv = (const float*)d_in[10]; const float* sa_bv = (const float*)d_in[11];
    const float* sa_wo = (const float*)d_in[12]; const float* sa_bo = (const float*)d_in[13];
    const float* sa_nq = (const float*)d_in[14]; const float* sa_nk = (const float*)d_in[15];
    const float* ca_wq = (const float*)d_in[16]; const float* ca_bq = (const float*)d_in[17];
    const float* ca_wk = (const float*)d_in[18]; const float* ca_bk = (const float*)d_in[19];
    const float* ca_wv = (const float*)d_in[20]; const float* ca_bv = (const float*)d_in[21];
    const float* ca_wo = (const float*)d_in[22]; const float* ca_bo = (const float*)d_in[23];
    const float* ca_nq = (const float*)d_in[24]; const float* ca_nk = (const float*)d_in[25];
    const float* n3_w  = (const float*)d_in[26]; const float* n3_b  = (const float*)d_in[27];
    const float* w1    = (const float*)d_in[28]; const float* b1    = (const float*)d_in[29];
    const float* w2    = (const float*)d_in[30]; const float* b2    = (const float*)d_in[31];
    float* out = (float*)d_out;

    float *em, *cb, *sb2, *xb;
    __half *tmph, *qh, *kh, *vhp, *xn, *y, *h, *ctxh, *wt;
    cudaGetSymbolAddress((void**)&em,   g_em);
    cudaGetSymbolAddress((void**)&cb,   g_cos);
    cudaGetSymbolAddress((void**)&sb2,  g_sin);
    cudaGetSymbolAddress((void**)&xb,   g_x);
    cudaGetSymbolAddress((void**)&tmph, g_tmp);
    cudaGetSymbolAddress((void**)&qh,   g_qh);
    cudaGetSymbolAddress((void**)&kh,   g_kh);
    cudaGetSymbolAddress((void**)&vhp,  g_vh);
    cudaGetSymbolAddress((void**)&xn,   g_xn);
    cudaGetSymbolAddress((void**)&y,    g_y);
    cudaGetSymbolAddress((void**)&h,    g_h);
    cudaGetSymbolAddress((void**)&ctxh, g_ctx);
    cudaGetSymbolAddress((void**)&wt,   g_wt);

    cudaFuncSetAttribute(k_attn_h, cudaFuncAttributeMaxDynamicSharedMemorySize, ATTN_H_SMEM);
    cudaFuncSetAttribute(k_gemm3<0,float>,  cudaFuncAttributeMaxDynamicSharedMemorySize, V3_SMEM);
    cudaFuncSetAttribute(k_gemm3<0,__half>, cudaFuncAttributeMaxDynamicSharedMemorySize, V3_SMEM);
    cudaFuncSetAttribute(k_gemm3<1,__half>, cudaFuncAttributeMaxDynamicSharedMemorySize, V3_SMEM);
    cudaFuncSetAttribute(k_gemm3<2,float>,  cudaFuncAttributeMaxDynamicSharedMemorySize, V3_SMEM);
    cudaFuncSetAttribute(k_gemm3<3,float>,  cudaFuncAttributeMaxDynamicSharedMemorySize, V3_SMEM);

    const float QSC = 0.08838834764831845f;  // 1/sqrt(128)

    dim3 blk(256);
    dim3 gblk(128);
    dim3 gP(DIMM/128, M1/128);
    dim3 gC(DIMM/128, MC/128);
    dim3 gF1(FFN/128, M1/128);
    dim3 gF2(DIMM/128, M1/128);
    dim3 gA(SS/128, HEADS, BB);      // 128-row Q tiles

    const int NW = DIMM*DIMM;        // 4M elems
    const int NF = DIMM*FFN;         // 16M elems

    // ---- pre-pass: straight fp32->fp16 converts ----
    k_h8<<<NW/8/256, blk>>>(sa_wq, wt + WT_Q,  NW);
    k_h8<<<NW/8/256, blk>>>(sa_wk, wt + WT_K,  NW);
    k_h8<<<NW/8/256, blk>>>(sa_wv, wt + WT_V,  NW);
    k_h8<<<NW/8/256, blk>>>(sa_wo, wt + WT_O,  NW);
    k_h8<<<NW/8/256, blk>>>(ca_wq, wt + WT_CQ, NW);
    k_h8<<<NW/8/256, blk>>>(ca_wk, wt + WT_CK, NW);
    k_h8<<<NW/8/256, blk>>>(ca_wv, wt + WT_CV, NW);
    k_h8<<<NW/8/256, blk>>>(ca_wo, wt + WT_CO, NW);
    k_h8<<<NF/8/256, blk>>>(w1,    wt + WT_F1, NF);
    k_h8<<<NF/8/256, blk>>>(w2,    wt + WT_F2, NF);
    k_h8<<<(MC*DIMM)/8/256, blk>>>(context, ctxh, MC*DIMM);
    k_embed<<<(BB*6*DIMM + 255)/256, blk>>>(modu, e, em);
    k_ropetab<<<(SS*64 + 255)/256, blk>>>(fcos, fsin, cb, sb2);

    // ---- self attention ----
    k_ln<<<M1, blk>>>(x, em + 1*DIMM, em + 0*DIMM, 1, xn);
    k_gemm3<0,__half><<<gP, gblk, V3_SMEM>>>(xn, wt + WT_Q, sa_bq, nullptr, nullptr, tmph, M1, DIMM, DIMM);
    k_rms_t<<<M1, blk>>>(tmph, sa_nq, qh, SS, 1, QSC);
    k_gemm3<0,__half><<<gP, gblk, V3_SMEM>>>(xn, wt + WT_K, sa_bk, nullptr, nullptr, tmph, M1, DIMM, DIMM);
    k_rms_t<<<M1, blk>>>(tmph, sa_nk, kh, SS, 1, 1.f);
    k_gemm3<0,__half><<<gP, gblk, V3_SMEM>>>(xn, wt + WT_V, sa_bv, nullptr, nullptr, vhp, M1, DIMM, DIMM);
    k_attn_h<<<gA, blk, ATTN_H_SMEM>>>(qh, kh, vhp, y, SS);
    k_gemm3<3,float><<<gP, gblk, V3_SMEM>>>(y, wt + WT_O, sa_bo, x, em + 2*DIMM, xb, M1, DIMM, DIMM);

    // ---- cross attention ----
    k_ln<<<M1, blk>>>(xb, n3_w, n3_b, 0, xn);
    k_gemm3<0,__half><<<gP, gblk, V3_SMEM>>>(xn, wt + WT_CQ, ca_bq, nullptr, nullptr, tmph, M1, DIMM, DIMM);
    k_rms_t<<<M1, blk>>>(tmph, ca_nq, qh, SS, 0, QSC);
    k_gemm3<0,__half><<<gC, gblk, V3_SMEM>>>(ctxh, wt + WT_CK, ca_bk, nullptr, nullptr, tmph, MC, DIMM, DIMM);
    k_rms_t<<<MC, blk>>>(tmph, ca_nk, kh, CTX, 0, 1.f);
    k_gemm3<0,__half><<<gC, gblk, V3_SMEM>>>(ctxh, wt + WT_CV, ca_bv, nullptr, nullptr, vhp, MC, DIMM, DIMM);
    k_attn_h<<<gA, blk, ATTN_H_SMEM>>>(qh, kh, vhp, y, CTX);
    k_gemm3<2,float><<<gP, gblk, V3_SMEM>>>(y, wt + WT_CO, ca_bo, xb, nullptr, xb, M1, DIMM, DIMM);

    // ---- FFN ----
    k_ln<<<M1, blk>>>(xb, em + 4*DIMM, em + 3*DIMM, 1, xn);
    k_gemm3<1,__half><<<gF1, gblk, V3_SMEM>>>(xn, wt + WT_F1, b1, nullptr, nullptr, h, M1, FFN, DIMM);
    k_gemm3<3,float><<<gF2, gblk, V3_SMEM>>>(h, wt + WT_F2, b2, xb, em + 5*DIMM, out, M1, DIMM, FFN);
}

// round 12
// speedup vs baseline: 1.3282x; 1.0431x over previous
#include <cuda_runtime.h>
#include <cuda_fp16.h>
#include <math.h>
#include <stddef.h>
#include <stdint.h>

// ---------------- problem constants ----------------
#define BB     2
#define SS     2048
#define DIMM   2048
#define HEADS  16
#define HD     128
#define FFN    8192
#define CTX    512
#define M1     (BB*SS)
#define MC     (BB*CTX)
#define EMSTR  (6*DIMM)
#define EPSF   1e-6f

// ---------------- device scratch ----------------
__device__ float g_em [BB*6*DIMM];
__device__ float g_cos[SS*(HD/2)];
__device__ float g_sin[SS*(HD/2)];
__device__ __align__(128) __half g_xb [M1*DIMM];     // residual stream (fp16)
__device__ __align__(128) __half g_tmp[M1*DIMM];     // pre-norm q/k (fp16)
__device__ __align__(128) __half g_qh [BB*HEADS*SS*HD];
__device__ __align__(128) __half g_kh [BB*HEADS*SS*HD];
__device__ __align__(128) __half g_vh [M1*DIMM];
__device__ __align__(128) __half g_xn [M1*DIMM];
__device__ __align__(128) __half g_y  [M1*DIMM];
__device__ __align__(128) __half g_h  [(size_t)M1*FFN];
__device__ __align__(128) __half g_ctx[MC*DIMM];
__device__ __align__(128) __half g_wt [64*1024*1024];

#define WT_Q   ((size_t)0)
#define WT_K   ((size_t)4*1024*1024)
#define WT_V   ((size_t)8*1024*1024)
#define WT_O   ((size_t)12*1024*1024)
#define WT_CQ  ((size_t)16*1024*1024)
#define WT_CK  ((size_t)20*1024*1024)
#define WT_CV  ((size_t)24*1024*1024)
#define WT_CO  ((size_t)28*1024*1024)
#define WT_F1  ((size_t)32*1024*1024)
#define WT_F2  ((size_t)48*1024*1024)

// ---------------- helpers ----------------
__device__ __forceinline__ void cp16(void* smem, const void* g) {
    unsigned s = (unsigned)__cvta_generic_to_shared(smem);
    asm volatile("cp.async.cg.shared.global [%0], [%1], 16;\n" :: "r"(s), "l"(g));
}
__device__ __forceinline__ void cp_commit() { asm volatile("cp.async.commit_group;\n"); }
__device__ __forceinline__ void cp_wait0()  { asm volatile("cp.async.wait_group 0;\n"); }
__device__ __forceinline__ void cp_wait1()  { asm volatile("cp.async.wait_group 1;\n"); }
__device__ __forceinline__ void cp_wait2()  { asm volatile("cp.async.wait_group 2;\n"); }

__device__ __forceinline__ void mma16816(float* d, const unsigned* a, const unsigned* b) {
    asm volatile(
        "mma.sync.aligned.m16n8k16.row.col.f32.f16.f16.f32 "
        "{%0,%1,%2,%3}, {%4,%5,%6,%7}, {%8,%9}, {%0,%1,%2,%3};\n"
        : "+f"(d[0]), "+f"(d[1]), "+f"(d[2]), "+f"(d[3])
        : "r"(a[0]), "r"(a[1]), "r"(a[2]), "r"(a[3]), "r"(b[0]), "r"(b[1]));
}
__device__ __forceinline__ void ldsm4(unsigned* r, unsigned saddr) {
    asm volatile("ldmatrix.sync.aligned.m8n8.x4.shared.b16 {%0,%1,%2,%3}, [%4];\n"
                 : "=r"(r[0]), "=r"(r[1]), "=r"(r[2]), "=r"(r[3]) : "r"(saddr));
}
__device__ __forceinline__ void ldsm4t(unsigned& r0, unsigned& r1, unsigned& r2, unsigned& r3,
                                       unsigned saddr) {
    asm volatile("ldmatrix.sync.aligned.m8n8.x4.trans.shared.b16 {%0,%1,%2,%3}, [%4];\n"
                 : "=r"(r0), "=r"(r1), "=r"(r2), "=r"(r3) : "r"(saddr));
}
__device__ __forceinline__ unsigned packh2(float a, float b) {
    __half2 h = __floats2half2_rn(a, b);
    return *reinterpret_cast<unsigned*>(&h);
}

template<typename OT> __device__ __forceinline__ void stv(OT* p, float v);
template<> __device__ __forceinline__ void stv<float >(float*  p, float v) { *p = v; }
template<> __device__ __forceinline__ void stv<__half>(__half* p, float v) { *p = __float2half(v); }
template<typename RT> __device__ __forceinline__ float ldv(const RT* p);
template<> __device__ __forceinline__ float ldv<float >(const float*  p) { return *p; }
template<> __device__ __forceinline__ float ldv<__half>(const __half* p) { return __half2float(*p); }

// load 8 contiguous elems as floats
__device__ __forceinline__ void ld8(const float* p, float* v) {
    float4 a = *(const float4*)p, b = *(const float4*)(p + 4);
    v[0]=a.x; v[1]=a.y; v[2]=a.z; v[3]=a.w; v[4]=b.x; v[5]=b.y; v[6]=b.z; v[7]=b.w;
}
__device__ __forceinline__ void ld8(const __half* p, float* v) {
    uint4 u = *(const uint4*)p;
    __half2 h0 = *(__half2*)&u.x, h1 = *(__half2*)&u.y;
    __half2 h2 = *(__half2*)&u.z, h3 = *(__half2*)&u.w;
    float2 f0 = __half22float2(h0), f1 = __half22float2(h1);
    float2 f2 = __half22float2(h2), f3 = __half22float2(h3);
    v[0]=f0.x; v[1]=f0.y; v[2]=f1.x; v[3]=f1.y; v[4]=f2.x; v[5]=f2.y; v[6]=f3.x; v[7]=f3.y;
}
__device__ __forceinline__ void st8h(__half* p, const float* v) {
    uint4 u;
    u.x = packh2(v[0], v[1]); u.y = packh2(v[2], v[3]);
    u.z = packh2(v[4], v[5]); u.w = packh2(v[6], v[7]);
    *(uint4*)p = u;
}

// ---------------- small kernels ----------------
__global__ void k_embed(const float* __restrict__ mo, const float* __restrict__ e,
                        float* __restrict__ em) {
    int i = blockIdx.x*256 + threadIdx.x;
    if (i < BB*6*DIMM) em[i] = mo[i % EMSTR] + e[i];
}

__global__ void k_ropetab(const float* __restrict__ fc, const float* __restrict__ fs,
                          float* __restrict__ cb, float* __restrict__ sb) {
    int i = blockIdx.x*256 + threadIdx.x;
    if (i >= SS*64) return;
    int s = i >> 6, d = i & 63;
    int f = s >> 8, h = (s >> 4) & 15, w = s & 15;
    int row = (d < 22) ? f : ((d < 43) ? h : w);
    cb[i] = fc[row*64 + d];
    sb[i] = fs[row*64 + d];
}

// vectorized fp32 -> fp16 convert (8 elems/thread)
__global__ void k_h8(const float* __restrict__ in, __half* __restrict__ out, int n) {
    int i = (blockIdx.x*256 + threadIdx.x)*8;
    if (i < n) {
        float v[8];
        ld8(in + i, v);
        st8h(out + i, v);
    }
}

// One-pass LayerNorm: 256 threads, 8 cols/thread, fused (sum,sumsq) reduction.
template<typename IT>
__global__ void k_ln(const IT* __restrict__ x, const float* __restrict__ scv,
                     const float* __restrict__ shv, int em_mode, __half* __restrict__ out) {
    __shared__ float red1[256], red2[256];
    int row = blockIdx.x, tid = threadIdx.x;
    int c0 = tid*8;
    float v[8];
    ld8(x + (size_t)row*DIMM + c0, v);
    float s1 = 0.f, s2 = 0.f;
#pragma unroll
    for (int i = 0; i < 8; i++) { s1 += v[i]; s2 += v[i]*v[i]; }
    red1[tid] = s1; red2[tid] = s2; __syncthreads();
    for (int s = 128; s > 0; s >>= 1) {
        if (tid < s) { red1[tid] += red1[tid+s]; red2[tid] += red2[tid+s]; }
        __syncthreads();
    }
    float m = red1[0] * (1.f/DIMM);
    float inv = rsqrtf(red2[0]*(1.f/DIMM) - m*m + EPSF);
    int bo = (row >> 11) * EMSTR;
    float sc[8], sh[8], o[8];
    if (em_mode) {
        ld8(scv + bo + c0, sc);
        ld8(shv + bo + c0, sh);
#pragma unroll
        for (int i = 0; i < 8; i++) o[i] = (v[i]-m)*inv*(1.f + sc[i]) + sh[i];
    } else {
        ld8(scv + c0, sc);
        ld8(shv + c0, sh);
#pragma unroll
        for (int i = 0; i < 8; i++) o[i] = (v[i]-m)*inv*sc[i] + sh[i];
    }
    st8h(out + (size_t)row*DIMM + c0, o);
}

// One-pass RMS norm + optional RoPE + transpose to [B,H,L,HD]
__global__ void k_rms_t(const __half* __restrict__ in, const float* __restrict__ w,
                        __half* __restrict__ outT, int L, int do_rope, float oscale) {
    __shared__ float red[256];
    int row = blockIdx.x, tid = threadIdx.x;
    int b = row / L, s = row % L;
    int c0 = tid*8;
    float v[8];
    ld8(in + (size_t)row*DIMM + c0, v);
    float s2 = 0.f;
#pragma unroll
    for (int i = 0; i < 8; i++) s2 += v[i]*v[i];
    red[tid] = s2; __syncthreads();
    for (int st = 128; st > 0; st >>= 1) {
        if (tid < st) red[tid] += red[tid+st];
        __syncthreads();
    }
    float inv = rsqrtf(red[0]*(1.f/DIMM) + EPSF) * oscale;
    float wv[8], o[8];
    ld8(w + c0, wv);
    int hh = c0 >> 7, hd0 = c0 & 127;
    __half* ob = outT + ((size_t)(b*HEADS + hh)*L + s)*HD + hd0;
    if (do_rope) {
#pragma unroll
        for (int j = 0; j < 4; j++) {
            int i = ((c0 >> 1) + j) & 63;
            float vr = v[2*j]   * wv[2*j]   * inv;
            float vi = v[2*j+1] * wv[2*j+1] * inv;
            float c = g_cos[s*64 + i], sn = g_sin[s*64 + i];
            o[2*j]   = vr*c - vi*sn;
            o[2*j+1] = vr*sn + vi*c;
        }
    } else {
#pragma unroll
        for (int i = 0; i < 8; i++) o[i] = v[i]*inv*wv[i];
    }
    st8h(ob, o);
}

// ---------------- fp16 tensor-core GEMM v3 (R9 core, res-type templated) ----------------
#define GLDH   40                       // A smem row halves (80B)
#define BLDH   136                      // B smem row halves (272B)
#define V3_A   (128*GLDH)
#define V3_B   (32*BLDH)
#define V3_STG (V3_A + V3_B)            // 9472 halves = 18944 B
#define V3_SMEM (4*V3_STG*2)            // 75776 B
template<int EPI, typename RT, typename OT>
__global__ __launch_bounds__(128, 2)
void k_gemm3(const __half* __restrict__ A, const __half* __restrict__ Bw,
             const float* __restrict__ bias, const RT* __restrict__ res,
             const float* __restrict__ gate, OT* __restrict__ C,
             int M, int N, int K) {
    extern __shared__ __half sm[];
    int tid = threadIdx.x;
    int w = tid >> 5, lane = tid & 31;
    int bm = blockIdx.y << 7, bn = blockIdx.x << 7;
    const __half* Ab = A + (size_t)bm*K;

    int wm = (w >> 1)*64, wn = (w & 1)*64;
    int r = lane >> 2, cc = lane & 3;
    int mat = lane >> 3, lr = lane & 7;
    int lrow = (lane & 7) + ((lane >> 3) & 1)*8;
    int lcol = (lane >> 4)*8;

    unsigned aoff[4], boff[4];
#pragma unroll
    for (int mi = 0; mi < 4; mi++)
        aoff[mi] = ((wm + mi*16 + ((mat & 1) << 3) + lr)*GLDH + ((mat >> 1) << 3)) * 2;
#pragma unroll
    for (int nj = 0; nj < 4; nj++)
        boff[nj] = (unsigned)((lrow*BLDH + wn + nj*16 + lcol) * 2);

    float acc[4][8][4];
#pragma unroll
    for (int i = 0; i < 4; i++)
#pragma unroll
        for (int j = 0; j < 8; j++)
#pragma unroll
            for (int t = 0; t < 4; t++) acc[i][j][t] = 0.f;

    auto stage = [&](int s, int kt) {
        __half* As = sm + s*V3_STG;
        __half* Bs = As + V3_A;
        int k0 = kt*32;
#pragma unroll
        for (int i2 = 0; i2 < 4; i2++) {
            int ch = tid + i2*128;
            int arow = ch >> 2, asg = ch & 3;
            cp16(&As[arow*GLDH + asg*8], Ab + (size_t)arow*K + k0 + asg*8);
            int brow = ch >> 4, bsg = ch & 15;
            cp16(&Bs[brow*BLDH + bsg*8], Bw + (size_t)(k0 + brow)*N + bn + bsg*8);
        }
        cp_commit();
    };

    int nk = K >> 5;
    stage(0, 0); stage(1, 1); stage(2, 2);
    for (int kt = 0; kt < nk; kt++) {
        cp_wait2();
        __syncthreads();
        if (kt + 3 < nk) stage((kt+3) & 3, kt+3);
        else             cp_commit();
        int st = kt & 3;
        unsigned abase = (unsigned)__cvta_generic_to_shared(sm + st*V3_STG);
        unsigned bbase = abase + V3_A*2;
#pragma unroll
        for (int ks = 0; ks < 2; ks++) {
            unsigned af[4][4], bf[4][4];
#pragma unroll
            for (int mi = 0; mi < 4; mi++) ldsm4(af[mi], abase + aoff[mi] + ks*32);
#pragma unroll
            for (int nj = 0; nj < 4; nj++)
                ldsm4t(bf[nj][0], bf[nj][1], bf[nj][2], bf[nj][3],
                       bbase + boff[nj] + (unsigned)(ks*16*BLDH*2));
#pragma unroll
            for (int mi = 0; mi < 4; mi++)
#pragma unroll
                for (int nj = 0; nj < 4; nj++) {
                    mma16816(acc[mi][2*nj],     af[mi], &bf[nj][0]);
                    mma16816(acc[mi][2*nj + 1], af[mi], &bf[nj][2]);
                }
        }
        __syncthreads();
    }

    // epilogue
#pragma unroll
    for (int mi = 0; mi < 4; mi++) {
        int row0 = bm + wm + mi*16 + r;
#pragma unroll
        for (int nj = 0; nj < 8; nj++) {
            int col0 = bn + wn + nj*8 + 2*cc;
#pragma unroll
            for (int t = 0; t < 4; t++) {
                int rr  = row0 + ((t >> 1) ? 8 : 0);
                int col = col0 + (t & 1);
                float v = acc[mi][nj][t] + bias[col];
                if (EPI == 1) {
                    float u = v;
                    float z = 0.7978845608028654f*(u + 0.044715f*u*u*u);
                    v = __fdividef(u, 1.f + __expf(-2.f*z));
                }
                if (EPI == 2) v += ldv(&res[(size_t)rr*N + col]);
                if (EPI == 3) v = ldv(&res[(size_t)rr*N + col]) + v * gate[(rr >> 11)*EMSTR + col];
                stv(&C[(size_t)rr*N + col], v);
            }
        }
    }
}

// ---------------- fp16 flash attention (exact R9 version) ----------------
#define AT_LDS 136
#define KVSZ   (64*AT_LDS)
#define ATTN_H_SMEM (4*KVSZ*2)
__global__ __launch_bounds__(128)
void k_attn_h(const __half* __restrict__ qt, const __half* __restrict__ kt,
              const __half* __restrict__ vh, __half* __restrict__ y, int Lk) {
    extern __shared__ __half smh[];
    __half* Kb = smh;
    __half* Vb = smh + 2*KVSZ;

    int tid = threadIdx.x;
    int w = tid >> 5, lane = tid & 31;
    int r = lane >> 2, cc = lane & 3;
    int qtile = blockIdx.x, hh = blockIdx.y, b = blockIdx.z;

    const __half* qb = qt + ((size_t)(b*HEADS + hh)*SS + qtile*64) * HD;
    const __half* kb = kt + (size_t)(b*HEADS + hh)*Lk*HD;
    const __half* vb = vh + (size_t)b*Lk*DIMM + hh*HD;

    auto stage_kv = [&](int st, int t2) {
        __half* Kd = Kb + st*KVSZ;
        __half* Vd = Vb + st*KVSZ;
#pragma unroll
        for (int i2 = 0; i2 < 8; i2++) {
            int ch = tid + i2*128;
            int row = ch >> 4, sg = ch & 15;
            cp16(&Kd[row*AT_LDS + sg*8], kb + (size_t)(t2*64 + row)*HD + sg*8);
            cp16(&Vd[row*AT_LDS + sg*8], vb + (size_t)(t2*64 + row)*DIMM + sg*8);
        }
        cp_commit();
    };

    {
        __half* Qd = Kb + KVSZ;
#pragma unroll
        for (int i2 = 0; i2 < 8; i2++) {
            int ch = tid + i2*128;
            int row = ch >> 4, sg = ch & 15;
            cp16(&Qd[row*AT_LDS + sg*8], qb + (size_t)row*HD + sg*8);
        }
        stage_kv(0, 0);
    }
    cp_wait0();
    __syncthreads();

    unsigned afrq[8][4];
    {
        const __half* Qs = Kb + KVSZ;
#pragma unroll
        for (int kc = 0; kc < 8; kc++) {
            int row = w*16 + r, col = kc*16 + 2*cc;
            afrq[kc][0] = *(const unsigned*)&Qs[row*AT_LDS + col];
            afrq[kc][1] = *(const unsigned*)&Qs[(row+8)*AT_LDS + col];
            afrq[kc][2] = *(const unsigned*)&Qs[row*AT_LDS + col + 8];
            afrq[kc][3] = *(const unsigned*)&Qs[(row+8)*AT_LDS + col + 8];
        }
    }

    float acc[16][4];
#pragma unroll
    for (int i = 0; i < 16; i++)
#pragma unroll
        for (int t = 0; t < 4; t++) acc[i][t] = 0.f;
    float m0 = -1e30f, m1 = -1e30f, l0 = 0.f, l1 = 0.f;

    int ntiles = Lk >> 6;
    for (int t2 = 0; t2 < ntiles; t2++) {
        __syncthreads();
        if (t2 + 1 < ntiles) { stage_kv((t2+1) & 1, t2+1); cp_wait1(); }
        else                 { cp_wait0(); }
        __syncthreads();
        const __half* Ks = Kb + (t2&1)*KVSZ;
        const __half* Vs = Vb + (t2&1)*KVSZ;

        float sacc[8][4];
#pragma unroll
        for (int nb = 0; nb < 8; nb++)
#pragma unroll
            for (int t = 0; t < 4; t++) sacc[nb][t] = 0.f;
#pragma unroll
        for (int kc = 0; kc < 8; kc++) {
            unsigned bfr[8][2];
            int col = kc*16 + 2*cc;
#pragma unroll
            for (int nb = 0; nb < 8; nb++) {
                int krow = nb*8 + r;
                bfr[nb][0] = *(const unsigned*)&Ks[krow*AT_LDS + col];
                bfr[nb][1] = *(const unsigned*)&Ks[krow*AT_LDS + col + 8];
            }
#pragma unroll
            for (int nb = 0; nb < 8; nb++) mma16816(sacc[nb], afrq[kc], bfr[nb]);
        }

        float mx0 = -1e30f, mx1 = -1e30f;
#pragma unroll
        for (int nb = 0; nb < 8; nb++) {
            mx0 = fmaxf(mx0, fmaxf(sacc[nb][0], sacc[nb][1]));
            mx1 = fmaxf(mx1, fmaxf(sacc[nb][2], sacc[nb][3]));
        }
        mx0 = fmaxf(mx0, __shfl_xor_sync(0xffffffffu, mx0, 1));
        mx0 = fmaxf(mx0, __shfl_xor_sync(0xffffffffu, mx0, 2));
        mx1 = fmaxf(mx1, __shfl_xor_sync(0xffffffffu, mx1, 1));
        mx1 = fmaxf(mx1, __shfl_xor_sync(0xffffffffu, mx1, 2));
        float mn0 = fmaxf(m0, mx0), mn1 = fmaxf(m1, mx1);
        float esc0 = __expf(m0 - mn0), esc1 = __expf(m1 - mn1);
        m0 = mn0; m1 = mn1;
        float ls0 = 0.f, ls1 = 0.f;
#pragma unroll
        for (int nb = 0; nb < 8; nb++) {
            sacc[nb][0] = __expf(sacc[nb][0] - mn0); ls0 += sacc[nb][0];
            sacc[nb][1] = __expf(sacc[nb][1] - mn0); ls0 += sacc[nb][1];
            sacc[nb][2] = __expf(sacc[nb][2] - mn1); ls1 += sacc[nb][2];
            sacc[nb][3] = __expf(sacc[nb][3] - mn1); ls1 += sacc[nb][3];
        }
        ls0 += __shfl_xor_sync(0xffffffffu, ls0, 1);
        ls0 += __shfl_xor_sync(0xffffffffu, ls0, 2);
        ls1 += __shfl_xor_sync(0xffffffffu, ls1, 1);
        ls1 += __shfl_xor_sync(0xffffffffu, ls1, 2);
        l0 = l0*esc0 + ls0;
        l1 = l1*esc1 + ls1;

        unsigned pf[4][4];
#pragma unroll
        for (int kc = 0; kc < 4; kc++) {
            pf[kc][0] = packh2(sacc[2*kc][0],   sacc[2*kc][1]);
            pf[kc][1] = packh2(sacc[2*kc][2],   sacc[2*kc][3]);
            pf[kc][2] = packh2(sacc[2*kc+1][0], sacc[2*kc+1][1]);
            pf[kc][3] = packh2(sacc[2*kc+1][2], sacc[2*kc+1][3]);
        }
#pragma unroll
        for (int nb = 0; nb < 16; nb++) {
            acc[nb][0] *= esc0; acc[nb][1] *= esc0;
            acc[nb][2] *= esc1; acc[nb][3] *= esc1;
        }

        unsigned vbase = (unsigned)__cvta_generic_to_shared(Vs);
        int lrow = (lane & 7) + ((lane >> 3) & 1)*8;
        int lcol = (lane >> 4)*8;
#pragma unroll
        for (int np = 0; np < 8; np++) {
#pragma unroll
            for (int kc = 0; kc < 4; kc++) {
                unsigned r0, r1, r2, r3;
                unsigned addr = vbase + (unsigned)(((kc*16 + lrow)*AT_LDS + np*16 + lcol)*2);
                ldsm4t(r0, r1, r2, r3, addr);
                unsigned b0[2] = {r0, r1};
                unsigned b1[2] = {r2, r3};
                mma16816(acc[np*2],     pf[kc], b0);
                mma16816(acc[np*2 + 1], pf[kc], b1);
            }
        }
    }

    float inv0 = 1.f/l0, inv1 = 1.f/l1;
    int row0 = qtile*64 + w*16 + r;
    __half* yb = y + (size_t)b*SS*DIMM + hh*HD;
#pragma unroll
    for (int nb = 0; nb < 16; nb++) {
        int col = nb*8 + 2*cc;
        __half2 h0 = __floats2half2_rn(acc[nb][0]*inv0, acc[nb][1]*inv0);
        __half2 h1 = __floats2half2_rn(acc[nb][2]*inv1, acc[nb][3]*inv1);
        *(__half2*)&yb[(size_t)row0*DIMM + col]     = h0;
        *(__half2*)&yb[(size_t)(row0+8)*DIMM + col] = h1;
    }
}

// ---------------- host ----------------
extern "C" void kernel_launch(void* const* d_in, const int* in_sizes, int n_in,
                              void* d_out, int out_size) {
    const float* x       = (const float*)d_in[0];
    const float* e       = (const float*)d_in[1];
    const float* context = (const float*)d_in[2];
    const float* fcos    = (const float*)d_in[3];
    const float* fsin    = (const float*)d_in[4];
    const float* modu    = (const float*)d_in[5];
    const float* sa_wq = (const float*)d_in[6];  const float* sa_bq = (const float*)d_in[7];
    const float* sa_wk = (const float*)d_in[8];  const float* sa_bk = (const float*)d_in[9];
    const float* sa_wv = (const float*)d_in[10]; const float* sa_bv = (const float*)d_in[11];
    const float* sa_wo = (const float*)d_in[12]; const float* sa_bo = (const float*)d_in[13];
    const float* sa_nq = (const float*)d_in[14]; const float* sa_nk = (const float*)d_in[15];
    const float* ca_wq = (const float*)d_in[16]; const float* ca_bq = (const float*)d_in[17];
    const float* ca_wk = (const float*)d_in[18]; const float* ca_bk = (const float*)d_in[19];
    const float* ca_wv = (const float*)d_in[20]; const float* ca_bv = (const float*)d_in[21];
    const float* ca_wo = (const float*)d_in[22]; const float* ca_bo = (const float*)d_in[23];
    const float* ca_nq = (const float*)d_in[24]; const float* ca_nk = (const float*)d_in[25];
    const float* n3_w  = (const float*)d_in[26]; const float* n3_b  = (const float*)d_in[27];
    const float* w1    = (const float*)d_in[28]; const float* b1    = (const float*)d_in[29];
    const float* w2    = (const float*)d_in[30]; const float* b2    = (const float*)d_in[31];
    float* out = (float*)d_out;

    float *em, *cb, *sb2;
    __half *xbh, *tmph, *qh, *kh, *vhp, *xn, *y, *h, *ctxh, *wt;
    cudaGetSymbolAddress((void**)&em,   g_em);
    cudaGetSymbolAddress((void**)&cb,   g_cos);
    cudaGetSymbolAddress((void**)&sb2,  g_sin);
    cudaGetSymbolAddress((void**)&xbh,  g_xb);
    cudaGetSymbolAddress((void**)&tmph, g_tmp);
    cudaGetSymbolAddress((void**)&qh,   g_qh);
    cudaGetSymbolAddress((void**)&kh,   g_kh);
    cudaGetSymbolAddress((void**)&vhp,  g_vh);
    cudaGetSymbolAddress((void**)&xn,   g_xn);
    cudaGetSymbolAddress((void**)&y,    g_y);
    cudaGetSymbolAddress((void**)&h,    g_h);
    cudaGetSymbolAddress((void**)&ctxh, g_ctx);
    cudaGetSymbolAddress((void**)&wt,   g_wt);

    cudaFuncSetAttribute(k_attn_h, cudaFuncAttributeMaxDynamicSharedMemorySize, ATTN_H_SMEM);
    cudaFuncSetAttribute((const void*)k_gemm3<0,float,__half>,   cudaFuncAttributeMaxDynamicSharedMemorySize, V3_SMEM);
    cudaFuncSetAttribute((const void*)k_gemm3<1,float,__half>,   cudaFuncAttributeMaxDynamicSharedMemorySize, V3_SMEM);
    cudaFuncSetAttribute((const void*)k_gemm3<2,__half,__half>,  cudaFuncAttributeMaxDynamicSharedMemorySize, V3_SMEM);
    cudaFuncSetAttribute((const void*)k_gemm3<3,float,__half>,   cudaFuncAttributeMaxDynamicSharedMemorySize, V3_SMEM);
    cudaFuncSetAttribute((const void*)k_gemm3<3,__half,float>,   cudaFuncAttributeMaxDynamicSharedMemorySize, V3_SMEM);

    const float QSC = 0.08838834764831845f;  // 1/sqrt(128)

    dim3 blk(256);
    dim3 gblk(128);
    dim3 gP(DIMM/128, M1/128);
    dim3 gC(DIMM/128, MC/128);
    dim3 gF1(FFN/128, M1/128);
    dim3 gF2(DIMM/128, M1/128);
    dim3 gA(SS/64, HEADS, BB);

    const int NW = DIMM*DIMM;
    const int NF = DIMM*FFN;

    // ---- pre-pass ----
    k_h8<<<NW/8/256, blk>>>(sa_wq, wt + WT_Q,  NW);
    k_h8<<<NW/8/256, blk>>>(sa_wk, wt + WT_K,  NW);
    k_h8<<<NW/8/256, blk>>>(sa_wv, wt + WT_V,  NW);
    k_h8<<<NW/8/256, blk>>>(sa_wo, wt + WT_O,  NW);
    k_h8<<<NW/8/256, blk>>>(ca_wq, wt + WT_CQ, NW);
    k_h8<<<NW/8/256, blk>>>(ca_wk, wt + WT_CK, NW);
    k_h8<<<NW/8/256, blk>>>(ca_wv, wt + WT_CV, NW);
    k_h8<<<NW/8/256, blk>>>(ca_wo, wt + WT_CO, NW);
    k_h8<<<NF/8/256, blk>>>(w1,    wt + WT_F1, NF);
    k_h8<<<NF/8/256, blk>>>(w2,    wt + WT_F2, NF);
    k_h8<<<(MC*DIMM)/8/256, blk>>>(context, ctxh, MC*DIMM);
    k_embed<<<(BB*6*DIMM + 255)/256, blk>>>(modu, e, em);
    k_ropetab<<<(SS*64 + 255)/256, blk>>>(fcos, fsin, cb, sb2);

    // ---- self attention ----
    k_ln<float><<<M1, blk>>>(x, em + 1*DIMM, em + 0*DIMM, 1, xn);
    k_gemm3<0,float,__half><<<gP, gblk, V3_SMEM>>>(xn, wt + WT_Q, sa_bq, nullptr, nullptr, tmph, M1, DIMM, DIMM);
    k_rms_t<<<M1, blk>>>(tmph, sa_nq, qh, SS, 1, QSC);
    k_gemm3<0,float,__half><<<gP, gblk, V3_SMEM>>>(xn, wt + WT_K, sa_bk, nullptr, nullptr, tmph, M1, DIMM, DIMM);
    k_rms_t<<<M1, blk>>>(tmph, sa_nk, kh, SS, 1, 1.f);
    k_gemm3<0,float,__half><<<gP, gblk, V3_SMEM>>>(xn, wt + WT_V, sa_bv, nullptr, nullptr, vhp, M1, DIMM, DIMM);
    k_attn_h<<<gA, gblk, ATTN_H_SMEM>>>(qh, kh, vhp, y, SS);
    k_gemm3<3,float,__half><<<gP, gblk, V3_SMEM>>>(y, wt + WT_O, sa_bo, x, em + 2*DIMM, xbh, M1, DIMM, DIMM);

    // ---- cross attention ----
    k_ln<__half><<<M1, blk>>>(xbh, n3_w, n3_b, 0, xn);
    k_gemm3<0,float,__half><<<gP, gblk, V3_SMEM>>>(xn, wt + WT_CQ, ca_bq, nullptr, nullptr, tmph, M1, DIMM, DIMM);
    k_rms_t<<<M1, blk>>>(tmph, ca_nq, qh, SS, 0, QSC);
    k_gemm3<0,float,__half><<<gC, gblk, V3_SMEM>>>(ctxh, wt + WT_CK, ca_bk, nullptr, nullptr, tmph, MC, DIMM, DIMM);
    k_rms_t<<<MC, blk>>>(tmph, ca_nk, kh, CTX, 0, 1.f);
    k_gemm3<0,float,__half><<<gC, gblk, V3_SMEM>>>(ctxh, wt + WT_CV, ca_bv, nullptr, nullptr, vhp, MC, DIMM, DIMM);
    k_attn_h<<<gA, gblk, ATTN_H_SMEM>>>(qh, kh, vhp, y, CTX);
    k_gemm3<2,__half,__half><<<gP, gblk, V3_SMEM>>>(y, wt + WT_CO, ca_bo, xbh, nullptr, xbh, M1, DIMM, DIMM);

    // ---- FFN ----
    k_ln<__half><<<M1, blk>>>(xbh, em + 4*DIMM, em + 3*DIMM, 1, xn);
    k_gemm3<1,float,__half><<<gF1, gblk, V3_SMEM>>>(xn, wt + WT_F1, b1, nullptr, nullptr, h, M1, FFN, DIMM);
    k_gemm3<3,__half,float><<<gF2, gblk, V3_SMEM>>>(h, wt + WT_F2, b2, xbh, em + 5*DIMM, out, M1, DIMM, FFN);
}

// round 14
// speedup vs baseline: 1.3514x; 1.0175x over previous
#include <cuda_runtime.h>
#include <cuda_fp16.h>
#include <math.h>
#include <stddef.h>
#include <stdint.h>

// ---------------- problem constants ----------------
#define BB     2
#define SS     2048
#define DIMM   2048
#define HEADS  16
#define HD     128
#define FFN    8192
#define CTX    512
#define M1     (BB*SS)
#define MC     (BB*CTX)
#define EMSTR  (6*DIMM)
#define EPSF   1e-6f

// ---------------- device scratch ----------------
__device__ float g_em [BB*6*DIMM];
__device__ float g_cos[SS*(HD/2)];
__device__ float g_sin[SS*(HD/2)];
__device__ __align__(128) __half g_xb [M1*DIMM];
__device__ __align__(128) __half g_tmp[M1*DIMM];
__device__ __align__(128) __half g_qh [BB*HEADS*SS*HD];
__device__ __align__(128) __half g_kh [BB*HEADS*SS*HD];
__device__ __align__(128) __half g_vh [M1*DIMM];
__device__ __align__(128) __half g_xn [M1*DIMM];
__device__ __align__(128) __half g_y  [M1*DIMM];
__device__ __align__(128) __half g_h  [(size_t)M1*FFN];
__device__ __align__(128) __half g_ctx[MC*DIMM];
__device__ __align__(128) __half g_wt [64*1024*1024];

#define WT_Q   ((size_t)0)
#define WT_K   ((size_t)4*1024*1024)
#define WT_V   ((size_t)8*1024*1024)
#define WT_O   ((size_t)12*1024*1024)
#define WT_CQ  ((size_t)16*1024*1024)
#define WT_CK  ((size_t)20*1024*1024)
#define WT_CV  ((size_t)24*1024*1024)
#define WT_CO  ((size_t)28*1024*1024)
#define WT_F1  ((size_t)32*1024*1024)
#define WT_F2  ((size_t)48*1024*1024)

// ---------------- helpers ----------------
__device__ __forceinline__ void cp16(void* smem, const void* g) {
    unsigned s = (unsigned)__cvta_generic_to_shared(smem);
    asm volatile("cp.async.cg.shared.global [%0], [%1], 16;\n" :: "r"(s), "l"(g));
}
__device__ __forceinline__ void cp_commit() { asm volatile("cp.async.commit_group;\n"); }
__device__ __forceinline__ void cp_wait0()  { asm volatile("cp.async.wait_group 0;\n"); }
__device__ __forceinline__ void cp_wait2()  { asm volatile("cp.async.wait_group 2;\n"); }

__device__ __forceinline__ void mma16816(float* d, const unsigned* a, const unsigned* b) {
    asm volatile(
        "mma.sync.aligned.m16n8k16.row.col.f32.f16.f16.f32 "
        "{%0,%1,%2,%3}, {%4,%5,%6,%7}, {%8,%9}, {%0,%1,%2,%3};\n"
        : "+f"(d[0]), "+f"(d[1]), "+f"(d[2]), "+f"(d[3])
        : "r"(a[0]), "r"(a[1]), "r"(a[2]), "r"(a[3]), "r"(b[0]), "r"(b[1]));
}
__device__ __forceinline__ void ldsm4(unsigned* r, unsigned saddr) {
    asm volatile("ldmatrix.sync.aligned.m8n8.x4.shared.b16 {%0,%1,%2,%3}, [%4];\n"
                 : "=r"(r[0]), "=r"(r[1]), "=r"(r[2]), "=r"(r[3]) : "r"(saddr));
}
__device__ __forceinline__ void ldsm4t(unsigned& r0, unsigned& r1, unsigned& r2, unsigned& r3,
                                       unsigned saddr) {
    asm volatile("ldmatrix.sync.aligned.m8n8.x4.trans.shared.b16 {%0,%1,%2,%3}, [%4];\n"
                 : "=r"(r0), "=r"(r1), "=r"(r2), "=r"(r3) : "r"(saddr));
}
__device__ __forceinline__ unsigned packh2(float a, float b) {
    __half2 h = __floats2half2_rn(a, b);
    return *reinterpret_cast<unsigned*>(&h);
}

template<typename OT> __device__ __forceinline__ void stv(OT* p, float v);
template<> __device__ __forceinline__ void stv<float >(float*  p, float v) { *p = v; }
template<> __device__ __forceinline__ void stv<__half>(__half* p, float v) { *p = __float2half(v); }
template<typename RT> __device__ __forceinline__ float ldv(const RT* p);
template<> __device__ __forceinline__ float ldv<float >(const float*  p) { return *p; }
template<> __device__ __forceinline__ float ldv<__half>(const __half* p) { return __half2float(*p); }

__device__ __forceinline__ void ld8(const float* p, float* v) {
    float4 a = *(const float4*)p, b = *(const float4*)(p + 4);
    v[0]=a.x; v[1]=a.y; v[2]=a.z; v[3]=a.w; v[4]=b.x; v[5]=b.y; v[6]=b.z; v[7]=b.w;
}
__device__ __forceinline__ void ld8(const __half* p, float* v) {
    uint4 u = *(const uint4*)p;
    __half2 h0 = *(__half2*)&u.x, h1 = *(__half2*)&u.y;
    __half2 h2 = *(__half2*)&u.z, h3 = *(__half2*)&u.w;
    float2 f0 = __half22float2(h0), f1 = __half22float2(h1);
    float2 f2 = __half22float2(h2), f3 = __half22float2(h3);
    v[0]=f0.x; v[1]=f0.y; v[2]=f1.x; v[3]=f1.y; v[4]=f2.x; v[5]=f2.y; v[6]=f3.x; v[7]=f3.y;
}
__device__ __forceinline__ void st8h(__half* p, const float* v) {
    uint4 u;
    u.x = packh2(v[0], v[1]); u.y = packh2(v[2], v[3]);
    u.z = packh2(v[4], v[5]); u.w = packh2(v[6], v[7]);
    *(uint4*)p = u;
}

// ---------------- small kernels ----------------
__global__ void k_embed(const float* __restrict__ mo, const float* __restrict__ e,
                        float* __restrict__ em) {
    int i = blockIdx.x*256 + threadIdx.x;
    if (i < BB*6*DIMM) em[i] = mo[i % EMSTR] + e[i];
}

__global__ void k_ropetab(const float* __restrict__ fc, const float* __restrict__ fs,
                          float* __restrict__ cb, float* __restrict__ sb) {
    int i = blockIdx.x*256 + threadIdx.x;
    if (i >= SS*64) return;
    int s = i >> 6, d = i & 63;
    int f = s >> 8, h = (s >> 4) & 15, w = s & 15;
    int row = (d < 22) ? f : ((d < 43) ? h : w);
    cb[i] = fc[row*64 + d];
    sb[i] = fs[row*64 + d];
}

// fused multi-segment fp32->fp16 convert: one launch, 16 elems/thread
#define NSEG 11
struct CvtArgs {
    const float* src[NSEG];
    __half*      dst[NSEG];
    int          end[NSEG];
};
__global__ void k_cvt_all(CvtArgs a, int total_chunks) {
    int ch = blockIdx.x*256 + threadIdx.x;
    if (ch >= total_chunks) return;
    int seg = 0;
#pragma unroll
    for (int i = 0; i < NSEG-1; i++) seg += (ch >= a.end[i]);
    int base = (seg == 0) ? 0 : a.end[seg-1];
    size_t off = (size_t)(ch - base) * 16;
    const float* s = a.src[seg] + off;
    __half* d = a.dst[seg] + off;
    float v0[8], v1[8];
    ld8(s, v0); ld8(s + 8, v1);
    st8h(d, v0); st8h(d + 8, v1);
}

// One-pass LayerNorm
template<typename IT>
__global__ void k_ln(const IT* __restrict__ x, const float* __restrict__ scv,
                     const float* __restrict__ shv, int em_mode, __half* __restrict__ out) {
    __shared__ float red1[256], red2[256];
    int row = blockIdx.x, tid = threadIdx.x;
    int c0 = tid*8;
    float v[8];
    ld8(x + (size_t)row*DIMM + c0, v);
    float s1 = 0.f, s2 = 0.f;
#pragma unroll
    for (int i = 0; i < 8; i++) { s1 += v[i]; s2 += v[i]*v[i]; }
    red1[tid] = s1; red2[tid] = s2; __syncthreads();
    for (int s = 128; s > 0; s >>= 1) {
        if (tid < s) { red1[tid] += red1[tid+s]; red2[tid] += red2[tid+s]; }
        __syncthreads();
    }
    float m = red1[0] * (1.f/DIMM);
    float inv = rsqrtf(red2[0]*(1.f/DIMM) - m*m + EPSF);
    int bo = (row >> 11) * EMSTR;
    float sc[8], sh[8], o[8];
    if (em_mode) {
        ld8(scv + bo + c0, sc);
        ld8(shv + bo + c0, sh);
#pragma unroll
        for (int i = 0; i < 8; i++) o[i] = (v[i]-m)*inv*(1.f + sc[i]) + sh[i];
    } else {
        ld8(scv + c0, sc);
        ld8(shv + c0, sh);
#pragma unroll
        for (int i = 0; i < 8; i++) o[i] = (v[i]-m)*inv*sc[i] + sh[i];
    }
    st8h(out + (size_t)row*DIMM + c0, o);
}

// One-pass RMS norm + optional RoPE + transpose
__global__ void k_rms_t(const __half* __restrict__ in, const float* __restrict__ w,
                        __half* __restrict__ outT, int L, int do_rope, float oscale) {
    __shared__ float red[256];
    int row = blockIdx.x, tid = threadIdx.x;
    int b = row / L, s = row % L;
    int c0 = tid*8;
    float v[8];
    ld8(in + (size_t)row*DIMM + c0, v);
    float s2 = 0.f;
#pragma unroll
    for (int i = 0; i < 8; i++) s2 += v[i]*v[i];
    red[tid] = s2; __syncthreads();
    for (int st = 128; st > 0; st >>= 1) {
        if (tid < st) red[tid] += red[tid+st];
        __syncthreads();
    }
    float inv = rsqrtf(red[0]*(1.f/DIMM) + EPSF) * oscale;
    float wv[8], o[8];
    ld8(w + c0, wv);
    int hh = c0 >> 7, hd0 = c0 & 127;
    __half* ob = outT + ((size_t)(b*HEADS + hh)*L + s)*HD + hd0;
    if (do_rope) {
#pragma unroll
        for (int j = 0; j < 4; j++) {
            int i = ((c0 >> 1) + j) & 63;
            float vr = v[2*j]   * wv[2*j]   * inv;
            float vi = v[2*j+1] * wv[2*j+1] * inv;
            float c = g_cos[s*64 + i], sn = g_sin[s*64 + i];
            o[2*j]   = vr*c - vi*sn;
            o[2*j+1] = vr*sn + vi*c;
        }
    } else {
#pragma unroll
        for (int i = 0; i < 8; i++) o[i] = v[i]*inv*wv[i];
    }
    st8h(ob, o);
}

// ---------------- fp16 tensor-core GEMM (single barrier per K-iter) ----------------
#define GLDH   40
#define BLDH   136
#define V3_A   (128*GLDH)
#define V3_B   (32*BLDH)
#define V3_STG (V3_A + V3_B)
#define V3_SMEM (4*V3_STG*2)
template<int EPI, typename RT, typename OT>
__global__ __launch_bounds__(128, 2)
void k_gemm3(const __half* __restrict__ A, const __half* __restrict__ Bw,
             const float* __restrict__ bias, const RT* __restrict__ res,
             const float* __restrict__ gate, OT* __restrict__ C,
             int M, int N, int K) {
    extern __shared__ __half sm[];
    int tid = threadIdx.x;
    int w = tid >> 5, lane = tid & 31;
    int bm = blockIdx.y << 7, bn = blockIdx.x << 7;
    const __half* Ab = A + (size_t)bm*K;

    int wm = (w >> 1)*64, wn = (w & 1)*64;
    int r = lane >> 2, cc = lane & 3;
    int mat = lane >> 3, lr = lane & 7;
    int lrow = (lane & 7) + ((lane >> 3) & 1)*8;
    int lcol = (lane >> 4)*8;

    unsigned aoff[4], boff[4];
#pragma unroll
    for (int mi = 0; mi < 4; mi++)
        aoff[mi] = ((wm + mi*16 + ((mat & 1) << 3) + lr)*GLDH + ((mat >> 1) << 3)) * 2;
#pragma unroll
    for (int nj = 0; nj < 4; nj++)
        boff[nj] = (unsigned)((lrow*BLDH + wn + nj*16 + lcol) * 2);

    float acc[4][8][4];
#pragma unroll
    for (int i = 0; i < 4; i++)
#pragma unroll
        for (int j = 0; j < 8; j++)
#pragma unroll
            for (int t = 0; t < 4; t++) acc[i][j][t] = 0.f;

    auto stage = [&](int s, int kt) {
        __half* As = sm + s*V3_STG;
        __half* Bs = As + V3_A;
        int k0 = kt*32;
#pragma unroll
        for (int i2 = 0; i2 < 4; i2++) {
            int ch = tid + i2*128;
            int arow = ch >> 2, asg = ch & 3;
            cp16(&As[arow*GLDH + asg*8], Ab + (size_t)arow*K + k0 + asg*8);
            int brow = ch >> 4, bsg = ch & 15;
            cp16(&Bs[brow*BLDH + bsg*8], Bw + (size_t)(k0 + brow)*N + bn + bsg*8);
        }
        cp_commit();
    };

    int nk = K >> 5;
    stage(0, 0); stage(1, 1); stage(2, 2);
    for (int kt = 0; kt < nk; kt++) {
        cp_wait2();
        __syncthreads();                       // single barrier per iteration
        if (kt + 3 < nk) stage((kt+3) & 3, kt+3);
        else             cp_commit();
        int st = kt & 3;
        unsigned abase = (unsigned)__cvta_generic_to_shared(sm + st*V3_STG);
        unsigned bbase = abase + V3_A*2;
#pragma unroll
        for (int ks = 0; ks < 2; ks++) {
            unsigned af[4][4], bf[4][4];
#pragma unroll
            for (int mi = 0; mi < 4; mi++) ldsm4(af[mi], abase + aoff[mi] + ks*32);
#pragma unroll
            for (int nj = 0; nj < 4; nj++)
                ldsm4t(bf[nj][0], bf[nj][1], bf[nj][2], bf[nj][3],
                       bbase + boff[nj] + (unsigned)(ks*16*BLDH*2));
#pragma unroll
            for (int mi = 0; mi < 4; mi++)
#pragma unroll
                for (int nj = 0; nj < 4; nj++) {
                    mma16816(acc[mi][2*nj],     af[mi], &bf[nj][0]);
                    mma16816(acc[mi][2*nj + 1], af[mi], &bf[nj][2]);
                }
        }
    }

    // epilogue
#pragma unroll
    for (int mi = 0; mi < 4; mi++) {
        int row0 = bm + wm + mi*16 + r;
#pragma unroll
        for (int nj = 0; nj < 8; nj++) {
            int col0 = bn + wn + nj*8 + 2*cc;
#pragma unroll
            for (int t = 0; t < 4; t++) {
                int rr  = row0 + ((t >> 1) ? 8 : 0);
                int col = col0 + (t & 1);
                float v = acc[mi][nj][t] + bias[col];
                if (EPI == 1) {
                    float u = v;
                    float z = 0.7978845608028654f*(u + 0.044715f*u*u*u);
                    v = __fdividef(u, 1.f + __expf(-2.f*z));
                }
                if (EPI == 2) v += ldv(&res[(size_t)rr*N + col]);
                if (EPI == 3) v = ldv(&res[(size_t)rr*N + col]) + v * gate[(rr >> 11)*EMSTR + col];
                stv(&C[(size_t)rr*N + col], v);
            }
        }
    }
}

// ---------------- fp16 flash attention (Q in prologue, single barrier per tile) ----------------
#define AT_LDS 136
#define KVSZ   (64*AT_LDS)
#define ATTN_H_SMEM (4*KVSZ*2)
__global__ __launch_bounds__(128)
void k_attn_h(const __half* __restrict__ qt, const __half* __restrict__ kt,
              const __half* __restrict__ vh, __half* __restrict__ y, int Lk) {
    extern __shared__ __half smh[];
    __half* Kb = smh;
    __half* Vb = smh + 2*KVSZ;

    int tid = threadIdx.x;
    int w = tid >> 5, lane = tid & 31;
    int r = lane >> 2, cc = lane & 3;
    int qtile = blockIdx.x, hh = blockIdx.y, b = blockIdx.z;

    const __half* qb = qt + ((size_t)(b*HEADS + hh)*SS + qtile*64) * HD;
    const __half* kb = kt + (size_t)(b*HEADS + hh)*Lk*HD;
    const __half* vb = vh + (size_t)b*Lk*DIMM + hh*HD;

    auto stage_kv = [&](int st, int t2) {
        __half* Kd = Kb + st*KVSZ;
        __half* Vd = Vb + st*KVSZ;
#pragma unroll
        for (int i2 = 0; i2 < 8; i2++) {
            int ch = tid + i2*128;
            int row = ch >> 4, sg = ch & 15;
            cp16(&Kd[row*AT_LDS + sg*8], kb + (size_t)(t2*64 + row)*HD + sg*8);
            cp16(&Vd[row*AT_LDS + sg*8], vb + (size_t)(t2*64 + row)*DIMM + sg*8);
        }
        cp_commit();
    };

    // prologue: Q tile (into Kb buf1) + KV tile0, one group
    {
        __half* Qd = Kb + KVSZ;
#pragma unroll
        for (int i2 = 0; i2 < 8; i2++) {
            int ch = tid + i2*128;
            int row = ch >> 4, sg = ch & 15;
            cp16(&Qd[row*AT_LDS + sg*8], qb + (size_t)row*HD + sg*8);
        }
        stage_kv(0, 0);
    }
    cp_wait0();
    __syncthreads();

    // Q fragments read BEFORE mainloop (buffer 1 not yet restaged; first restage is
    // stage_kv(1,1) inside t2=0, which every thread issues only after the t2=0 barrier,
    // i.e. after all threads have read Q here).
    unsigned afrq[8][4];
    {
        const __half* Qs = Kb + KVSZ;
#pragma unroll
        for (int kc = 0; kc < 8; kc++) {
            int row = w*16 + r, col = kc*16 + 2*cc;
            afrq[kc][0] = *(const unsigned*)&Qs[row*AT_LDS + col];
            afrq[kc][1] = *(const unsigned*)&Qs[(row+8)*AT_LDS + col];
            afrq[kc][2] = *(const unsigned*)&Qs[row*AT_LDS + col + 8];
            afrq[kc][3] = *(const unsigned*)&Qs[(row+8)*AT_LDS + col + 8];
        }
    }

    float acc[16][4];
#pragma unroll
    for (int i = 0; i < 16; i++)
#pragma unroll
        for (int t = 0; t < 4; t++) acc[i][t] = 0.f;
    float m0 = -1e30f, m1 = -1e30f, l0 = 0.f, l1 = 0.f;

    int ntiles = Lk >> 6;
    for (int t2 = 0; t2 < ntiles; t2++) {
        if (t2 > 0) cp_wait0();                  // waits exactly tile t2's group
        __syncthreads();                         // single barrier per tile
        if (t2 + 1 < ntiles) stage_kv((t2+1) & 1, t2+1);
        const __half* Ks = Kb + (t2&1)*KVSZ;
        const __half* Vs = Vb + (t2&1)*KVSZ;

        float sacc[8][4];
#pragma unroll
        for (int nb = 0; nb < 8; nb++)
#pragma unroll
            for (int t = 0; t < 4; t++) sacc[nb][t] = 0.f;
#pragma unroll
        for (int kc = 0; kc < 8; kc++) {
            unsigned bfr[8][2];
            int col = kc*16 + 2*cc;
#pragma unroll
            for (int nb = 0; nb < 8; nb++) {
                int krow = nb*8 + r;
                bfr[nb][0] = *(const unsigned*)&Ks[krow*AT_LDS + col];
                bfr[nb][1] = *(const unsigned*)&Ks[krow*AT_LDS + col + 8];
            }
#pragma unroll
            for (int nb = 0; nb < 8; nb++) mma16816(sacc[nb], afrq[kc], bfr[nb]);
        }

        float mx0 = -1e30f, mx1 = -1e30f;
#pragma unroll
        for (int nb = 0; nb < 8; nb++) {
            mx0 = fmaxf(mx0, fmaxf(sacc[nb][0], sacc[nb][1]));
            mx1 = fmaxf(mx1, fmaxf(sacc[nb][2], sacc[nb][3]));
        }
        mx0 = fmaxf(mx0, __shfl_xor_sync(0xffffffffu, mx0, 1));
        mx0 = fmaxf(mx0, __shfl_xor_sync(0xffffffffu, mx0, 2));
        mx1 = fmaxf(mx1, __shfl_xor_sync(0xffffffffu, mx1, 1));
        mx1 = fmaxf(mx1, __shfl_xor_sync(0xffffffffu, mx1, 2));
        float mn0 = fmaxf(m0, mx0), mn1 = fmaxf(m1, mx1);
        float esc0 = __expf(m0 - mn0), esc1 = __expf(m1 - mn1);
        m0 = mn0; m1 = mn1;
        float ls0 = 0.f, ls1 = 0.f;
#pragma unroll
        for (int nb = 0; nb < 8; nb++) {
            sacc[nb][0] = __expf(sacc[nb][0] - mn0); ls0 += sacc[nb][0];
            sacc[nb][1] = __expf(sacc[nb][1] - mn0); ls0 += sacc[nb][1];
            sacc[nb][2] = __expf(sacc[nb][2] - mn1); ls1 += sacc[nb][2];
            sacc[nb][3] = __expf(sacc[nb][3] - mn1); ls1 += sacc[nb][3];
        }
        ls0 += __shfl_xor_sync(0xffffffffu, ls0, 1);
        ls0 += __shfl_xor_sync(0xffffffffu, ls0, 2);
        ls1 += __shfl_xor_sync(0xffffffffu, ls1, 1);
        ls1 += __shfl_xor_sync(0xffffffffu, ls1, 2);
        l0 = l0*esc0 + ls0;
        l1 = l1*esc1 + ls1;

        unsigned pf[4][4];
#pragma unroll
        for (int kc = 0; kc < 4; kc++) {
            pf[kc][0] = packh2(sacc[2*kc][0],   sacc[2*kc][1]);
            pf[kc][1] = packh2(sacc[2*kc][2],   sacc[2*kc][3]);
            pf[kc][2] = packh2(sacc[2*kc+1][0], sacc[2*kc+1][1]);
            pf[kc][3] = packh2(sacc[2*kc+1][2], sacc[2*kc+1][3]);
        }
#pragma unroll
        for (int nb = 0; nb < 16; nb++) {
            acc[nb][0] *= esc0; acc[nb][1] *= esc0;
            acc[nb][2] *= esc1; acc[nb][3] *= esc1;
        }

        unsigned vbase = (unsigned)__cvta_generic_to_shared(Vs);
        int lrow = (lane & 7) + ((lane >> 3) & 1)*8;
        int lcol = (lane >> 4)*8;
#pragma unroll
        for (int np = 0; np < 8; np++) {
#pragma unroll
            for (int kc = 0; kc < 4; kc++) {
                unsigned r0, r1, r2, r3;
                unsigned addr = vbase + (unsigned)(((kc*16 + lrow)*AT_LDS + np*16 + lcol)*2);
                ldsm4t(r0, r1, r2, r3, addr);
                unsigned b0[2] = {r0, r1};
                unsigned b1[2] = {r2, r3};
                mma16816(acc[np*2],     pf[kc], b0);
                mma16816(acc[np*2 + 1], pf[kc], b1);
            }
        }
    }

    float inv0 = 1.f/l0, inv1 = 1.f/l1;
    int row0 = qtile*64 + w*16 + r;
    __half* yb = y + (size_t)b*SS*DIMM + hh*HD;
#pragma unroll
    for (int nb = 0; nb < 16; nb++) {
        int col = nb*8 + 2*cc;
        __half2 h0 = __floats2half2_rn(acc[nb][0]*inv0, acc[nb][1]*inv0);
        __half2 h1 = __floats2half2_rn(acc[nb][2]*inv1, acc[nb][3]*inv1);
        *(__half2*)&yb[(size_t)row0*DIMM + col]     = h0;
        *(__half2*)&yb[(size_t)(row0+8)*DIMM + col] = h1;
    }
}

// ---------------- host ----------------
extern "C" void kernel_launch(void* const* d_in, const int* in_sizes, int n_in,
                              void* d_out, int out_size) {
    const float* x       = (const float*)d_in[0];
    const float* e       = (const float*)d_in[1];
    const float* context = (const float*)d_in[2];
    const float* fcos    = (const float*)d_in[3];
    const float* fsin    = (const float*)d_in[4];
    const float* modu    = (const float*)d_in[5];
    const float* sa_wq = (const float*)d_in[6];  const float* sa_bq = (const float*)d_in[7];
    const float* sa_wk = (const float*)d_in[8];  const float* sa_bk = (const float*)d_in[9];
    const float* sa_wv = (const float*)d_in[10]; const float* sa_bv = (const float*)d_in[11];
    const float* sa_wo = (const float*)d_in[12]; const float* sa_bo = (const float*)d_in[13];
    const float* sa_nq = (const float*)d_in[14]; const float* sa_nk = (const float*)d_in[15];
    const float* ca_wq = (const float*)d_in[16]; const float* ca_bq = (const float*)d_in[17];
    const float* ca_wk = (const float*)d_in[18]; const float* ca_bk = (const float*)d_in[19];
    const float* ca_wv = (const float*)d_in[20]; const float* ca_bv = (const float*)d_in[21];
    const float* ca_wo = (const float*)d_in[22]; const float* ca_bo = (const float*)d_in[23];
    const float* ca_nq = (const float*)d_in[24]; const float* ca_nk = (const float*)d_in[25];
    const float* n3_w  = (const float*)d_in[26]; const float* n3_b  = (const float*)d_in[27];
    const float* w1    = (const float*)d_in[28]; const float* b1    = (const float*)d_in[29];
    const float* w2    = (const float*)d_in[30]; const float* b2    = (const float*)d_in[31];
    float* out = (float*)d_out;

    float *em, *cb, *sb2;
    __half *xbh, *tmph, *qh, *kh, *vhp, *xn, *y, *h, *ctxh, *wt;
    cudaGetSymbolAddress((void**)&em,   g_em);
    cudaGetSymbolAddress((void**)&cb,   g_cos);
    cudaGetSymbolAddress((void**)&sb2,  g_sin);
    cudaGetSymbolAddress((void**)&xbh,  g_xb);
    cudaGetSymbolAddress((void**)&tmph, g_tmp);
    cudaGetSymbolAddress((void**)&qh,   g_qh);
    cudaGetSymbolAddress((void**)&kh,   g_kh);
    cudaGetSymbolAddress((void**)&vhp,  g_vh);
    cudaGetSymbolAddress((void**)&xn,   g_xn);
    cudaGetSymbolAddress((void**)&y,    g_y);
    cudaGetSymbolAddress((void**)&h,    g_h);
    cudaGetSymbolAddress((void**)&ctxh, g_ctx);
    cudaGetSymbolAddress((void**)&wt,   g_wt);

    cudaFuncSetAttribute(k_attn_h, cudaFuncAttributeMaxDynamicSharedMemorySize, ATTN_H_SMEM);
    cudaFuncSetAttribute((const void*)k_gemm3<0,float,__half>,   cudaFuncAttributeMaxDynamicSharedMemorySize, V3_SMEM);
    cudaFuncSetAttribute((const void*)k_gemm3<1,float,__half>,   cudaFuncAttributeMaxDynamicSharedMemorySize, V3_SMEM);
    cudaFuncSetAttribute((const void*)k_gemm3<2,__half,__half>,  cudaFuncAttributeMaxDynamicSharedMemorySize, V3_SMEM);
    cudaFuncSetAttribute((const void*)k_gemm3<3,float,__half>,   cudaFuncAttributeMaxDynamicSharedMemorySize, V3_SMEM);
    cudaFuncSetAttribute((const void*)k_gemm3<3,__half,float>,   cudaFuncAttributeMaxDynamicSharedMemorySize, V3_SMEM);

    const float QSC = 0.08838834764831845f;

    dim3 blk(256);
    dim3 gblk(128);
    dim3 gP(DIMM/128, M1/128);
    dim3 gC(DIMM/128, MC/128);
    dim3 gF1(FFN/128, M1/128);
    dim3 gF2(DIMM/128, M1/128);
    dim3 gA(SS/64, HEADS, BB);

    const int NW = DIMM*DIMM;
    const int NF = DIMM*FFN;

    // ---- fused pre-pass convert (one launch) ----
    {
        CvtArgs a;
        const float* srcs[NSEG] = { sa_wq, sa_wk, sa_wv, sa_wo, ca_wq, ca_wk, ca_wv, ca_wo,
                                    w1, w2, context };
        __half* dsts[NSEG] = { wt+WT_Q, wt+WT_K, wt+WT_V, wt+WT_O, wt+WT_CQ, wt+WT_CK,
                               wt+WT_CV, wt+WT_CO, wt+WT_F1, wt+WT_F2, ctxh };
        int sizes[NSEG] = { NW, NW, NW, NW, NW, NW, NW, NW, NF, NF, MC*DIMM };
        int cum = 0;
        for (int i = 0; i < NSEG; i++) {
            a.src[i] = srcs[i]; a.dst[i] = dsts[i];
            cum += sizes[i] / 16;
            a.end[i] = cum;
        }
        int total = cum;
        k_cvt_all<<<(total + 255)/256, blk>>>(a, total);
    }
    k_embed<<<(BB*6*DIMM + 255)/256, blk>>>(modu, e, em);
    k_ropetab<<<(SS*64 + 255)/256, blk>>>(fcos, fsin, cb, sb2);

    // ---- self attention ----
    k_ln<float><<<M1, blk>>>(x, em + 1*DIMM, em + 0*DIMM, 1, xn);
    k_gemm3<0,float,__half><<<gP, gblk, V3_SMEM>>>(xn, wt + WT_Q, sa_bq, nullptr, nullptr, tmph, M1, DIMM, DIMM);
    k_rms_t<<<M1, blk>>>(tmph, sa_nq, qh, SS, 1, QSC);
    k_gemm3<0,float,__half><<<gP, gblk, V3_SMEM>>>(xn, wt + WT_K, sa_bk, nullptr, nullptr, tmph, M1, DIMM, DIMM);
    k_rms_t<<<M1, blk>>>(tmph, sa_nk, kh, SS, 1, 1.f);
    k_gemm3<0,float,__half><<<gP, gblk, V3_SMEM>>>(xn, wt + WT_V, sa_bv, nullptr, nullptr, vhp, M1, DIMM, DIMM);
    k_attn_h<<<gA, gblk, ATTN_H_SMEM>>>(qh, kh, vhp, y, SS);
    k_gemm3<3,float,__half><<<gP, gblk, V3_SMEM>>>(y, wt + WT_O, sa_bo, x, em + 2*DIMM, xbh, M1, DIMM, DIMM);

    // ---- cross attention ----
    k_ln<__half><<<M1, blk>>>(xbh, n3_w, n3_b, 0, xn);
    k_gemm3<0,float,__half><<<gP, gblk, V3_SMEM>>>(xn, wt + WT_CQ, ca_bq, nullptr, nullptr, tmph, M1, DIMM, DIMM);
    k_rms_t<<<M1, blk>>>(tmph, ca_nq, qh, SS, 0, QSC);
    k_gemm3<0,float,__half><<<gC, gblk, V3_SMEM>>>(ctxh, wt + WT_CK, ca_bk, nullptr, nullptr, tmph, MC, DIMM, DIMM);
    k_rms_t<<<MC, blk>>>(tmph, ca_nk, kh, CTX, 0, 1.f);
    k_gemm3<0,float,__half><<<gC, gblk, V3_SMEM>>>(ctxh, wt + WT_CV, ca_bv, nullptr, nullptr, vhp, MC, DIMM, DIMM);
    k_attn_h<<<gA, gblk, ATTN_H_SMEM>>>(qh, kh, vhp, y, CTX);
    k_gemm3<2,__half,__half><<<gP, gblk, V3_SMEM>>>(y, wt + WT_CO, ca_bo, xbh, nullptr, xbh, M1, DIMM, DIMM);

    // ---- FFN ----
    k_ln<__half><<<M1, blk>>>(xbh, em + 4*DIMM, em + 3*DIMM, 1, xn);
    k_gemm3<1,float,__half><<<gF1, gblk, V3_SMEM>>>(xn, wt + WT_F1, b1, nullptr, nullptr, h, M1, FFN, DIMM);
    k_gemm3<3,__half,float><<<gF2, gblk, V3_SMEM>>>(h, wt + WT_F2, b2, xbh, em + 5*DIMM, out, M1, DIMM, FFN);
}

// round 15
// speedup vs baseline: 1.3610x; 1.0071x over previous
#include <cuda_runtime.h>
#include <cuda_fp16.h>
#include <math.h>
#include <stddef.h>
#include <stdint.h>

// ---------------- problem constants ----------------
#define BB     2
#define SS     2048
#define DIMM   2048
#define HEADS  16
#define HD     128
#define FFN    8192
#define CTX    512
#define M1     (BB*SS)
#define MC     (BB*CTX)
#define EMSTR  (6*DIMM)
#define EPSF   1e-6f

// ---------------- device scratch ----------------
__device__ float g_em [BB*6*DIMM];
__device__ float g_cos[SS*(HD/2)];
__device__ float g_sin[SS*(HD/2)];
__device__ __align__(128) __half g_xb [M1*DIMM];
__device__ __align__(128) __half g_tmp[M1*DIMM];
__device__ __align__(128) __half g_qh [BB*HEADS*SS*HD];
__device__ __align__(128) __half g_kh [BB*HEADS*SS*HD];
__device__ __align__(128) __half g_vh [M1*DIMM];
__device__ __align__(128) __half g_xn [M1*DIMM];
__device__ __align__(128) __half g_y  [M1*DIMM];
__device__ __align__(128) __half g_h  [(size_t)M1*FFN];
__device__ __align__(128) __half g_ctx[MC*DIMM];
__device__ __align__(128) __half g_wt [64*1024*1024];

#define WT_Q   ((size_t)0)
#define WT_K   ((size_t)4*1024*1024)
#define WT_V   ((size_t)8*1024*1024)
#define WT_O   ((size_t)12*1024*1024)
#define WT_CQ  ((size_t)16*1024*1024)
#define WT_CK  ((size_t)20*1024*1024)
#define WT_CV  ((size_t)24*1024*1024)
#define WT_CO  ((size_t)28*1024*1024)
#define WT_F1  ((size_t)32*1024*1024)
#define WT_F2  ((size_t)48*1024*1024)

// ---------------- helpers ----------------
__device__ __forceinline__ void cp16(void* smem, const void* g) {
    unsigned s = (unsigned)__cvta_generic_to_shared(smem);
    asm volatile("cp.async.cg.shared.global [%0], [%1], 16;\n" :: "r"(s), "l"(g));
}
__device__ __forceinline__ void cp_commit() { asm volatile("cp.async.commit_group;\n"); }
__device__ __forceinline__ void cp_wait0()  { asm volatile("cp.async.wait_group 0;\n"); }
__device__ __forceinline__ void cp_wait2()  { asm volatile("cp.async.wait_group 2;\n"); }

__device__ __forceinline__ void mma16816(float* d, const unsigned* a, const unsigned* b) {
    asm volatile(
        "mma.sync.aligned.m16n8k16.row.col.f32.f16.f16.f32 "
        "{%0,%1,%2,%3}, {%4,%5,%6,%7}, {%8,%9}, {%0,%1,%2,%3};\n"
        : "+f"(d[0]), "+f"(d[1]), "+f"(d[2]), "+f"(d[3])
        : "r"(a[0]), "r"(a[1]), "r"(a[2]), "r"(a[3]), "r"(b[0]), "r"(b[1]));
}
__device__ __forceinline__ void ldsm4(unsigned* r, unsigned saddr) {
    asm volatile("ldmatrix.sync.aligned.m8n8.x4.shared.b16 {%0,%1,%2,%3}, [%4];\n"
                 : "=r"(r[0]), "=r"(r[1]), "=r"(r[2]), "=r"(r[3]) : "r"(saddr));
}
__device__ __forceinline__ void ldsm4t(unsigned& r0, unsigned& r1, unsigned& r2, unsigned& r3,
                                       unsigned saddr) {
    asm volatile("ldmatrix.sync.aligned.m8n8.x4.trans.shared.b16 {%0,%1,%2,%3}, [%4];\n"
                 : "=r"(r0), "=r"(r1), "=r"(r2), "=r"(r3) : "r"(saddr));
}
__device__ __forceinline__ unsigned packh2(float a, float b) {
    __half2 h = __floats2half2_rn(a, b);
    return *reinterpret_cast<unsigned*>(&h);
}

template<typename OT> __device__ __forceinline__ void stv(OT* p, float v);
template<> __device__ __forceinline__ void stv<float >(float*  p, float v) { *p = v; }
template<> __device__ __forceinline__ void stv<__half>(__half* p, float v) { *p = __float2half(v); }
template<typename RT> __device__ __forceinline__ float ldv(const RT* p);
template<> __device__ __forceinline__ float ldv<float >(const float*  p) { return *p; }
template<> __device__ __forceinline__ float ldv<__half>(const __half* p) { return __half2float(*p); }

__device__ __forceinline__ void ld8(const float* p, float* v) {
    float4 a = *(const float4*)p, b = *(const float4*)(p + 4);
    v[0]=a.x; v[1]=a.y; v[2]=a.z; v[3]=a.w; v[4]=b.x; v[5]=b.y; v[6]=b.z; v[7]=b.w;
}
__device__ __forceinline__ void ld8(const __half* p, float* v) {
    uint4 u = *(const uint4*)p;
    __half2 h0 = *(__half2*)&u.x, h1 = *(__half2*)&u.y;
    __half2 h2 = *(__half2*)&u.z, h3 = *(__half2*)&u.w;
    float2 f0 = __half22float2(h0), f1 = __half22float2(h1);
    float2 f2 = __half22float2(h2), f3 = __half22float2(h3);
    v[0]=f0.x; v[1]=f0.y; v[2]=f1.x; v[3]=f1.y; v[4]=f2.x; v[5]=f2.y; v[6]=f3.x; v[7]=f3.y;
}
__device__ __forceinline__ void st8h(__half* p, const float* v) {
    uint4 u;
    u.x = packh2(v[0], v[1]); u.y = packh2(v[2], v[3]);
    u.z = packh2(v[4], v[5]); u.w = packh2(v[6], v[7]);
    *(uint4*)p = u;
}
__device__ __forceinline__ float wred(float v) {
#pragma unroll
    for (int s = 16; s > 0; s >>= 1) v += __shfl_xor_sync(0xffffffffu, v, s);
    return v;
}

// ---------------- small kernels ----------------
__global__ void k_embed(const float* __restrict__ mo, const float* __restrict__ e,
                        float* __restrict__ em) {
    int i = blockIdx.x*256 + threadIdx.x;
    if (i < BB*6*DIMM) em[i] = mo[i % EMSTR] + e[i];
}

__global__ void k_ropetab(const float* __restrict__ fc, const float* __restrict__ fs,
                          float* __restrict__ cb, float* __restrict__ sb) {
    int i = blockIdx.x*256 + threadIdx.x;
    if (i >= SS*64) return;
    int s = i >> 6, d = i & 63;
    int f = s >> 8, h = (s >> 4) & 15, w = s & 15;
    int row = (d < 22) ? f : ((d < 43) ? h : w);
    cb[i] = fc[row*64 + d];
    sb[i] = fs[row*64 + d];
}

// fused multi-segment fp32->fp16 convert
#define NSEG 11
struct CvtArgs {
    const float* src[NSEG];
    __half*      dst[NSEG];
    int          end[NSEG];
};
__global__ void k_cvt_all(CvtArgs a, int total_chunks) {
    int ch = blockIdx.x*256 + threadIdx.x;
    if (ch >= total_chunks) return;
    int seg = 0;
#pragma unroll
    for (int i = 0; i < NSEG-1; i++) seg += (ch >= a.end[i]);
    int base = (seg == 0) ? 0 : a.end[seg-1];
    size_t off = (size_t)(ch - base) * 16;
    const float* s = a.src[seg] + off;
    __half* d = a.dst[seg] + off;
    float v0[8], v1[8];
    ld8(s, v0); ld8(s + 8, v1);
    st8h(d, v0); st8h(d + 8, v1);
}

// One-pass LayerNorm, warp-shuffle reduction (1 barrier)
template<typename IT>
__global__ void k_ln(const IT* __restrict__ x, const float* __restrict__ scv,
                     const float* __restrict__ shv, int em_mode, __half* __restrict__ out) {
    __shared__ float w1s[8], w2s[8];
    int row = blockIdx.x, tid = threadIdx.x;
    int wp = tid >> 5, lane = tid & 31;
    int c0 = tid*8;
    float v[8];
    ld8(x + (size_t)row*DIMM + c0, v);
    float s1 = 0.f, s2 = 0.f;
#pragma unroll
    for (int i = 0; i < 8; i++) { s1 += v[i]; s2 += v[i]*v[i]; }
    s1 = wred(s1); s2 = wred(s2);
    if (lane == 0) { w1s[wp] = s1; w2s[wp] = s2; }
    __syncthreads();
    float t1 = 0.f, t2 = 0.f;
#pragma unroll
    for (int i = 0; i < 8; i++) { t1 += w1s[i]; t2 += w2s[i]; }
    float m = t1 * (1.f/DIMM);
    float inv = rsqrtf(t2*(1.f/DIMM) - m*m + EPSF);
    int bo = (row >> 11) * EMSTR;
    float sc[8], sh[8], o[8];
    if (em_mode) {
        ld8(scv + bo + c0, sc);
        ld8(shv + bo + c0, sh);
#pragma unroll
        for (int i = 0; i < 8; i++) o[i] = (v[i]-m)*inv*(1.f + sc[i]) + sh[i];
    } else {
        ld8(scv + c0, sc);
        ld8(shv + c0, sh);
#pragma unroll
        for (int i = 0; i < 8; i++) o[i] = (v[i]-m)*inv*sc[i] + sh[i];
    }
    st8h(out + (size_t)row*DIMM + c0, o);
}

// One-pass RMS norm + optional RoPE + transpose, warp-shuffle reduction (1 barrier)
__global__ void k_rms_t(const __half* __restrict__ in, const float* __restrict__ w,
                        __half* __restrict__ outT, int L, int do_rope, float oscale) {
    __shared__ float ws[8];
    int row = blockIdx.x, tid = threadIdx.x;
    int wp = tid >> 5, lane = tid & 31;
    int b = row / L, s = row % L;
    int c0 = tid*8;
    float v[8];
    ld8(in + (size_t)row*DIMM + c0, v);
    float s2 = 0.f;
#pragma unroll
    for (int i = 0; i < 8; i++) s2 += v[i]*v[i];
    s2 = wred(s2);
    if (lane == 0) ws[wp] = s2;
    __syncthreads();
    float t2 = 0.f;
#pragma unroll
    for (int i = 0; i < 8; i++) t2 += ws[i];
    float inv = rsqrtf(t2*(1.f/DIMM) + EPSF) * oscale;
    float wv[8], o[8];
    ld8(w + c0, wv);
    int hh = c0 >> 7, hd0 = c0 & 127;
    __half* ob = outT + ((size_t)(b*HEADS + hh)*L + s)*HD + hd0;
    if (do_rope) {
#pragma unroll
        for (int j = 0; j < 4; j++) {
            int i = ((c0 >> 1) + j) & 63;
            float vr = v[2*j]   * wv[2*j]   * inv;
            float vi = v[2*j+1] * wv[2*j+1] * inv;
            float c = g_cos[s*64 + i], sn = g_sin[s*64 + i];
            o[2*j]   = vr*c - vi*sn;
            o[2*j+1] = vr*sn + vi*c;
        }
    } else {
#pragma unroll
        for (int i = 0; i < 8; i++) o[i] = v[i]*inv*wv[i];
    }
    st8h(ob, o);
}

// ---------------- fp16 tensor-core GEMM (single barrier per K-iter) ----------------
#define GLDH   40
#define BLDH   136
#define V3_A   (128*GLDH)
#define V3_B   (32*BLDH)
#define V3_STG (V3_A + V3_B)
#define V3_SMEM (4*V3_STG*2)
template<int EPI, typename RT, typename OT>
__global__ __launch_bounds__(128, 2)
void k_gemm3(const __half* __restrict__ A, const __half* __restrict__ Bw,
             const float* __restrict__ bias, const RT* __restrict__ res,
             const float* __restrict__ gate, OT* __restrict__ C,
             int M, int N, int K) {
    extern __shared__ __half sm[];
    int tid = threadIdx.x;
    int w = tid >> 5, lane = tid & 31;
    int bm = blockIdx.y << 7, bn = blockIdx.x << 7;
    const __half* Ab = A + (size_t)bm*K;

    int wm = (w >> 1)*64, wn = (w & 1)*64;
    int r = lane >> 2, cc = lane & 3;
    int mat = lane >> 3, lr = lane & 7;
    int lrow = (lane & 7) + ((lane >> 3) & 1)*8;
    int lcol = (lane >> 4)*8;

    unsigned aoff[4], boff[4];
#pragma unroll
    for (int mi = 0; mi < 4; mi++)
        aoff[mi] = ((wm + mi*16 + ((mat & 1) << 3) + lr)*GLDH + ((mat >> 1) << 3)) * 2;
#pragma unroll
    for (int nj = 0; nj < 4; nj++)
        boff[nj] = (unsigned)((lrow*BLDH + wn + nj*16 + lcol) * 2);

    float acc[4][8][4];
#pragma unroll
    for (int i = 0; i < 4; i++)
#pragma unroll
        for (int j = 0; j < 8; j++)
#pragma unroll
            for (int t = 0; t < 4; t++) acc[i][j][t] = 0.f;

    auto stage = [&](int s, int kt) {
        __half* As = sm + s*V3_STG;
        __half* Bs = As + V3_A;
        int k0 = kt*32;
#pragma unroll
        for (int i2 = 0; i2 < 4; i2++) {
            int ch = tid + i2*128;
            int arow = ch >> 2, asg = ch & 3;
            cp16(&As[arow*GLDH + asg*8], Ab + (size_t)arow*K + k0 + asg*8);
            int brow = ch >> 4, bsg = ch & 15;
            cp16(&Bs[brow*BLDH + bsg*8], Bw + (size_t)(k0 + brow)*N + bn + bsg*8);
        }
        cp_commit();
    };

    int nk = K >> 5;
    stage(0, 0); stage(1, 1); stage(2, 2);
    for (int kt = 0; kt < nk; kt++) {
        cp_wait2();
        __syncthreads();
        if (kt + 3 < nk) stage((kt+3) & 3, kt+3);
        else             cp_commit();
        int st = kt & 3;
        unsigned abase = (unsigned)__cvta_generic_to_shared(sm + st*V3_STG);
        unsigned bbase = abase + V3_A*2;
#pragma unroll
        for (int ks = 0; ks < 2; ks++) {
            unsigned af[4][4], bf[4][4];
#pragma unroll
            for (int mi = 0; mi < 4; mi++) ldsm4(af[mi], abase + aoff[mi] + ks*32);
#pragma unroll
            for (int nj = 0; nj < 4; nj++)
                ldsm4t(bf[nj][0], bf[nj][1], bf[nj][2], bf[nj][3],
                       bbase + boff[nj] + (unsigned)(ks*16*BLDH*2));
#pragma unroll
            for (int mi = 0; mi < 4; mi++)
#pragma unroll
                for (int nj = 0; nj < 4; nj++) {
                    mma16816(acc[mi][2*nj],     af[mi], &bf[nj][0]);
                    mma16816(acc[mi][2*nj + 1], af[mi], &bf[nj][2]);
                }
        }
    }

    // epilogue
#pragma unroll
    for (int mi = 0; mi < 4; mi++) {
        int row0 = bm + wm + mi*16 + r;
#pragma unroll
        for (int nj = 0; nj < 8; nj++) {
            int col0 = bn + wn + nj*8 + 2*cc;
#pragma unroll
            for (int t = 0; t < 4; t++) {
                int rr  = row0 + ((t >> 1) ? 8 : 0);
                int col = col0 + (t & 1);
                float v = acc[mi][nj][t] + bias[col];
                if (EPI == 1) {
                    float u = v;
                    float z = 0.7978845608028654f*(u + 0.044715f*u*u*u);
                    v = __fdividef(u, 1.f + __expf(-2.f*z));
                }
                if (EPI == 2) v += ldv(&res[(size_t)rr*N + col]);
                if (EPI == 3) v = ldv(&res[(size_t)rr*N + col]) + v * gate[(rr >> 11)*EMSTR + col];
                stv(&C[(size_t)rr*N + col], v);
            }
        }
    }
}

// ---------------- fp16 flash attention (Q in prologue, single barrier per tile) ----------------
#define AT_LDS 136
#define KVSZ   (64*AT_LDS)
#define ATTN_H_SMEM (4*KVSZ*2)
__global__ __launch_bounds__(128)
void k_attn_h(const __half* __restrict__ qt, const __half* __restrict__ kt,
              const __half* __restrict__ vh, __half* __restrict__ y, int Lk) {
    extern __shared__ __half smh[];
    __half* Kb = smh;
    __half* Vb = smh + 2*KVSZ;

    int tid = threadIdx.x;
    int w = tid >> 5, lane = tid & 31;
    int r = lane >> 2, cc = lane & 3;
    int qtile = blockIdx.x, hh = blockIdx.y, b = blockIdx.z;

    const __half* qb = qt + ((size_t)(b*HEADS + hh)*SS + qtile*64) * HD;
    const __half* kb = kt + (size_t)(b*HEADS + hh)*Lk*HD;
    const __half* vb = vh + (size_t)b*Lk*DIMM + hh*HD;

    auto stage_kv = [&](int st, int t2) {
        __half* Kd = Kb + st*KVSZ;
        __half* Vd = Vb + st*KVSZ;
#pragma unroll
        for (int i2 = 0; i2 < 8; i2++) {
            int ch = tid + i2*128;
            int row = ch >> 4, sg = ch & 15;
            cp16(&Kd[row*AT_LDS + sg*8], kb + (size_t)(t2*64 + row)*HD + sg*8);
            cp16(&Vd[row*AT_LDS + sg*8], vb + (size_t)(t2*64 + row)*DIMM + sg*8);
        }
        cp_commit();
    };

    {
        __half* Qd = Kb + KVSZ;
#pragma unroll
        for (int i2 = 0; i2 < 8; i2++) {
            int ch = tid + i2*128;
            int row = ch >> 4, sg = ch & 15;
            cp16(&Qd[row*AT_LDS + sg*8], qb + (size_t)row*HD + sg*8);
        }
        stage_kv(0, 0);
    }
    cp_wait0();
    __syncthreads();

    unsigned afrq[8][4];
    {
        const __half* Qs = Kb + KVSZ;
#pragma unroll
        for (int kc = 0; kc < 8; kc++) {
            int row = w*16 + r, col = kc*16 + 2*cc;
            afrq[kc][0] = *(const unsigned*)&Qs[row*AT_LDS + col];
            afrq[kc][1] = *(const unsigned*)&Qs[(row+8)*AT_LDS + col];
            afrq[kc][2] = *(const unsigned*)&Qs[row*AT_LDS + col + 8];
            afrq[kc][3] = *(const unsigned*)&Qs[(row+8)*AT_LDS + col + 8];
        }
    }

    float acc[16][4];
#pragma unroll
    for (int i = 0; i < 16; i++)
#pragma unroll
        for (int t = 0; t < 4; t++) acc[i][t] = 0.f;
    float m0 = -1e30f, m1 = -1e30f, l0 = 0.f, l1 = 0.f;

    int ntiles = Lk >> 6;
    for (int t2 = 0; t2 < ntiles; t2++) {
        if (t2 > 0) cp_wait0();
        __syncthreads();
        if (t2 + 1 < ntiles) stage_kv((t2+1) & 1, t2+1);
        const __half* Ks = Kb + (t2&1)*KVSZ;
        const __half* Vs = Vb + (t2&1)*KVSZ;

        float sacc[8][4];
#pragma unroll
        for (int nb = 0; nb < 8; nb++)
#pragma unroll
            for (int t = 0; t < 4; t++) sacc[nb][t] = 0.f;
#pragma unroll
        for (int kc = 0; kc < 8; kc++) {
            unsigned bfr[8][2];
            int col = kc*16 + 2*cc;
#pragma unroll
            for (int nb = 0; nb < 8; nb++) {
                int krow = nb*8 + r;
                bfr[nb][0] = *(const unsigned*)&Ks[krow*AT_LDS + col];
                bfr[nb][1] = *(const unsigned*)&Ks[krow*AT_LDS + col + 8];
            }
#pragma unroll
            for (int nb = 0; nb < 8; nb++) mma16816(sacc[nb], afrq[kc], bfr[nb]);
        }

        float mx0 = -1e30f, mx1 = -1e30f;
#pragma unroll
        for (int nb = 0; nb < 8; nb++) {
            mx0 = fmaxf(mx0, fmaxf(sacc[nb][0], sacc[nb][1]));
            mx1 = fmaxf(mx1, fmaxf(sacc[nb][2], sacc[nb][3]));
        }
        mx0 = fmaxf(mx0, __shfl_xor_sync(0xffffffffu, mx0, 1));
        mx0 = fmaxf(mx0, __shfl_xor_sync(0xffffffffu, mx0, 2));
        mx1 = fmaxf(mx1, __shfl_xor_sync(0xffffffffu, mx1, 1));
        mx1 = fmaxf(mx1, __shfl_xor_sync(0xffffffffu, mx1, 2));
        float mn0 = fmaxf(m0, mx0), mn1 = fmaxf(m1, mx1);
        float esc0 = __expf(m0 - mn0), esc1 = __expf(m1 - mn1);
        m0 = mn0; m1 = mn1;
        float ls0 = 0.f, ls1 = 0.f;
#pragma unroll
        for (int nb = 0; nb < 8; nb++) {
            sacc[nb][0] = __expf(sacc[nb][0] - mn0); ls0 += sacc[nb][0];
            sacc[nb][1] = __expf(sacc[nb][1] - mn0); ls0 += sacc[nb][1];
            sacc[nb][2] = __expf(sacc[nb][2] - mn1); ls1 += sacc[nb][2];
            sacc[nb][3] = __expf(sacc[nb][3] - mn1); ls1 += sacc[nb][3];
        }
        ls0 += __shfl_xor_sync(0xffffffffu, ls0, 1);
        ls0 += __shfl_xor_sync(0xffffffffu, ls0, 2);
        ls1 += __shfl_xor_sync(0xffffffffu, ls1, 1);
        ls1 += __shfl_xor_sync(0xffffffffu, ls1, 2);
        l0 = l0*esc0 + ls0;
        l1 = l1*esc1 + ls1;

        unsigned pf[4][4];
#pragma unroll
        for (int kc = 0; kc < 4; kc++) {
            pf[kc][0] = packh2(sacc[2*kc][0],   sacc[2*kc][1]);
            pf[kc][1] = packh2(sacc[2*kc][2],   sacc[2*kc][3]);
            pf[kc][2] = packh2(sacc[2*kc+1][0], sacc[2*kc+1][1]);
            pf[kc][3] = packh2(sacc[2*kc+1][2], sacc[2*kc+1][3]);
        }
#pragma unroll
        for (int nb = 0; nb < 16; nb++) {
            acc[nb][0] *= esc0; acc[nb][1] *= esc0;
            acc[nb][2] *= esc1; acc[nb][3] *= esc1;
        }

        unsigned vbase = (unsigned)__cvta_generic_to_shared(Vs);
        int lrow = (lane & 7) + ((lane >> 3) & 1)*8;
        int lcol = (lane >> 4)*8;
#pragma unroll
        for (int np = 0; np < 8; np++) {
#pragma unroll
            for (int kc = 0; kc < 4; kc++) {
                unsigned r0, r1, r2, r3;
                unsigned addr = vbase + (unsigned)(((kc*16 + lrow)*AT_LDS + np*16 + lcol)*2);
                ldsm4t(r0, r1, r2, r3, addr);
                unsigned b0[2] = {r0, r1};
                unsigned b1[2] = {r2, r3};
                mma16816(acc[np*2],     pf[kc], b0);
                mma16816(acc[np*2 + 1], pf[kc], b1);
            }
        }
    }

    float inv0 = 1.f/l0, inv1 = 1.f/l1;
    int row0 = qtile*64 + w*16 + r;
    __half* yb = y + (size_t)b*SS*DIMM + hh*HD;
#pragma unroll
    for (int nb = 0; nb < 16; nb++) {
        int col = nb*8 + 2*cc;
        __half2 h0 = __floats2half2_rn(acc[nb][0]*inv0, acc[nb][1]*inv0);
        __half2 h1 = __floats2half2_rn(acc[nb][2]*inv1, acc[nb][3]*inv1);
        *(__half2*)&yb[(size_t)row0*DIMM + col]     = h0;
        *(__half2*)&yb[(size_t)(row0+8)*DIMM + col] = h1;
    }
}

// ---------------- host ----------------
extern "C" void kernel_launch(void* const* d_in, const int* in_sizes, int n_in,
                              void* d_out, int out_size) {
    const float* x       = (const float*)d_in[0];
    const float* e       = (const float*)d_in[1];
    const float* context = (const float*)d_in[2];
    const float* fcos    = (const float*)d_in[3];
    const float* fsin    = (const float*)d_in[4];
    const float* modu    = (const float*)d_in[5];
    const float* sa_wq = (const float*)d_in[6];  const float* sa_bq = (const float*)d_in[7];
    const float* sa_wk = (const float*)d_in[8];  const float* sa_bk = (const float*)d_in[9];
    const float* sa_wv = (const float*)d_in[10]; const float* sa_bv = (const float*)d_in[11];
    const float* sa_wo = (const float*)d_in[12]; const float* sa_bo = (const float*)d_in[13];
    const float* sa_nq = (const float*)d_in[14]; const float* sa_nk = (const float*)d_in[15];
    const float* ca_wq = (const float*)d_in[16]; const float* ca_bq = (const float*)d_in[17];
    const float* ca_wk = (const float*)d_in[18]; const float* ca_bk = (const float*)d_in[19];
    const float* ca_wv = (const float*)d_in[20]; const float* ca_bv = (const float*)d_in[21];
    const float* ca_wo = (const float*)d_in[22]; const float* ca_bo = (const float*)d_in[23];
    const float* ca_nq = (const float*)d_in[24]; const float* ca_nk = (const float*)d_in[25];
    const float* n3_w  = (const float*)d_in[26]; const float* n3_b  = (const float*)d_in[27];
    const float* w1    = (const float*)d_in[28]; const float* b1    = (const float*)d_in[29];
    const float* w2    = (const float*)d_in[30]; const float* b2    = (const float*)d_in[31];
    float* out = (float*)d_out;

    float *em, *cb, *sb2;
    __half *xbh, *tmph, *qh, *kh, *vhp, *xn, *y, *h, *ctxh, *wt;
    cudaGetSymbolAddress((void**)&em,   g_em);
    cudaGetSymbolAddress((void**)&cb,   g_cos);
    cudaGetSymbolAddress((void**)&sb2,  g_sin);
    cudaGetSymbolAddress((void**)&xbh,  g_xb);
    cudaGetSymbolAddress((void**)&tmph, g_tmp);
    cudaGetSymbolAddress((void**)&qh,   g_qh);
    cudaGetSymbolAddress((void**)&kh,   g_kh);
    cudaGetSymbolAddress((void**)&vhp,  g_vh);
    cudaGetSymbolAddress((void**)&xn,   g_xn);
    cudaGetSymbolAddress((void**)&y,    g_y);
    cudaGetSymbolAddress((void**)&h,    g_h);
    cudaGetSymbolAddress((void**)&ctxh, g_ctx);
    cudaGetSymbolAddress((void**)&wt,   g_wt);

    cudaFuncSetAttribute(k_attn_h, cudaFuncAttributeMaxDynamicSharedMemorySize, ATTN_H_SMEM);
    cudaFuncSetAttribute((const void*)k_gemm3<0,float,__half>,   cudaFuncAttributeMaxDynamicSharedMemorySize, V3_SMEM);
    cudaFuncSetAttribute((const void*)k_gemm3<1,float,__half>,   cudaFuncAttributeMaxDynamicSharedMemorySize, V3_SMEM);
    cudaFuncSetAttribute((const void*)k_gemm3<2,__half,__half>,  cudaFuncAttributeMaxDynamicSharedMemorySize, V3_SMEM);
    cudaFuncSetAttribute((const void*)k_gemm3<3,float,__half>,   cudaFuncAttributeMaxDynamicSharedMemorySize, V3_SMEM);
    cudaFuncSetAttribute((const void*)k_gemm3<3,__half,float>,   cudaFuncAttributeMaxDynamicSharedMemorySize, V3_SMEM);

    const float QSC = 0.08838834764831845f;

    dim3 blk(256);
    dim3 gblk(128);
    dim3 gP(DIMM/128, M1/128);
    dim3 gC(DIMM/128, MC/128);
    dim3 gF1(FFN/128, M1/128);
    dim3 gF2(DIMM/128, M1/128);
    dim3 gA(SS/64, HEADS, BB);

    const int NW = DIMM*DIMM;
    const int NF = DIMM*FFN;

    // ---- fused pre-pass convert ----
    {
        CvtArgs a;
        const float* srcs[NSEG] = { sa_wq, sa_wk, sa_wv, sa_wo, ca_wq, ca_wk, ca_wv, ca_wo,
                                    w1, w2, context };
        __half* dsts[NSEG] = { wt+WT_Q, wt+WT_K, wt+WT_V, wt+WT_O, wt+WT_CQ, wt+WT_CK,
                               wt+WT_CV, wt+WT_CO, wt+WT_F1, wt+WT_F2, ctxh };
        int sizes[NSEG] = { NW, NW, NW, NW, NW, NW, NW, NW, NF, NF, MC*DIMM };
        int cum = 0;
        for (int i = 0; i < NSEG; i++) {
            a.src[i] = srcs[i]; a.dst[i] = dsts[i];
            cum += sizes[i] / 16;
            a.end[i] = cum;
        }
        int total = cum;
        k_cvt_all<<<(total + 255)/256, blk>>>(a, total);
    }
    k_embed<<<(BB*6*DIMM + 255)/256, blk>>>(modu, e, em);
    k_ropetab<<<(SS*64 + 255)/256, blk>>>(fcos, fsin, cb, sb2);

    // ---- self attention ----
    k_ln<float><<<M1, blk>>>(x, em + 1*DIMM, em + 0*DIMM, 1, xn);
    k_gemm3<0,float,__half><<<gP, gblk, V3_SMEM>>>(xn, wt + WT_Q, sa_bq, nullptr, nullptr, tmph, M1, DIMM, DIMM);
    k_rms_t<<<M1, blk>>>(tmph, sa_nq, qh, SS, 1, QSC);
    k_gemm3<0,float,__half><<<gP, gblk, V3_SMEM>>>(xn, wt + WT_K, sa_bk, nullptr, nullptr, tmph, M1, DIMM, DIMM);
    k_rms_t<<<M1, blk>>>(tmph, sa_nk, kh, SS, 1, 1.f);
    k_gemm3<0,float,__half><<<gP, gblk, V3_SMEM>>>(xn, wt + WT_V, sa_bv, nullptr, nullptr, vhp, M1, DIMM, DIMM);
    k_attn_h<<<gA, gblk, ATTN_H_SMEM>>>(qh, kh, vhp, y, SS);
    k_gemm3<3,float,__half><<<gP, gblk, V3_SMEM>>>(y, wt + WT_O, sa_bo, x, em + 2*DIMM, xbh, M1, DIMM, DIMM);

    // ---- cross attention ----
    k_ln<__half><<<M1, blk>>>(xbh, n3_w, n3_b, 0, xn);
    k_gemm3<0,float,__half><<<gP, gblk, V3_SMEM>>>(xn, wt + WT_CQ, ca_bq, nullptr, nullptr, tmph, M1, DIMM, DIMM);
    k_rms_t<<<M1, blk>>>(tmph, ca_nq, qh, SS, 0, QSC);
    k_gemm3<0,float,__half><<<gC, gblk, V3_SMEM>>>(ctxh, wt + WT_CK, ca_bk, nullptr, nullptr, tmph, MC, DIMM, DIMM);
    k_rms_t<<<MC, blk>>>(tmph, ca_nk, kh, CTX, 0, 1.f);
    k_gemm3<0,float,__half><<<gC, gblk, V3_SMEM>>>(ctxh, wt + WT_CV, ca_bv, nullptr, nullptr, vhp, MC, DIMM, DIMM);
    k_attn_h<<<gA, gblk, ATTN_H_SMEM>>>(qh, kh, vhp, y, CTX);
    k_gemm3<2,__half,__half><<<gP, gblk, V3_SMEM>>>(y, wt + WT_CO, ca_bo, xbh, nullptr, xbh, M1, DIMM, DIMM);

    // ---- FFN ----
    k_ln<__half><<<M1, blk>>>(xbh, em + 4*DIMM, em + 3*DIMM, 1, xn);
    k_gemm3<1,float,__half><<<gF1, gblk, V3_SMEM>>>(xn, wt + WT_F1, b1, nullptr, nullptr, h, M1, FFN, DIMM);
    k_gemm3<3,__half,float><<<gF2, gblk, V3_SMEM>>>(h, wt + WT_F2, b2, xbh, em + 5*DIMM, out, M1, DIMM, FFN);
}

// round 16
// speedup vs baseline: 1.3910x; 1.0220x over previous
#include <cuda_runtime.h>
#include <cuda_fp16.h>
#include <math.h>
#include <stddef.h>
#include <stdint.h>

// ---------------- problem constants ----------------
#define BB     2
#define SS     2048
#define DIMM   2048
#define HEADS  16
#define HD     128
#define FFN    8192
#define CTX    512
#define M1     (BB*SS)
#define MC     (BB*CTX)
#define EMSTR  (6*DIMM)
#define EPSF   1e-6f

// ---------------- device scratch ----------------
__device__ float g_em [BB*6*DIMM];
__device__ float g_cos[SS*(HD/2)];
__device__ float g_sin[SS*(HD/2)];
__device__ __align__(128) __half g_xb [M1*DIMM];
__device__ __align__(128) __half g_tmp[M1*DIMM];
__device__ __align__(128) __half g_qh [BB*HEADS*SS*HD];
__device__ __align__(128) __half g_kh [BB*HEADS*SS*HD];
__device__ __align__(128) __half g_vh [M1*DIMM];
__device__ __align__(128) __half g_xn [M1*DIMM];
__device__ __align__(128) __half g_y  [M1*DIMM];
__device__ __align__(128) __half g_h  [(size_t)M1*FFN];
__device__ __align__(128) __half g_ctx[MC*DIMM];
__device__ __align__(128) __half g_wt [64*1024*1024];

// wt offsets (halves)
#define OFF_QKV ((size_t)0)                    // [2048][6144]
#define OFF_O   ((size_t)12582912)             // [2048][2048]
#define OFF_CQ  ((size_t)16777216)
#define OFF_CKV ((size_t)20971520)             // [2048][4096]
#define OFF_CO  ((size_t)29360128)
#define OFF_F1  ((size_t)33554432)             // [2048][8192]
#define OFF_F2  ((size_t)50331648)             // [8192][2048]

// ---------------- helpers ----------------
__device__ __forceinline__ void cp16(void* smem, const void* g) {
    unsigned s = (unsigned)__cvta_generic_to_shared(smem);
    asm volatile("cp.async.cg.shared.global [%0], [%1], 16;\n" :: "r"(s), "l"(g));
}
__device__ __forceinline__ void cp_commit() { asm volatile("cp.async.commit_group;\n"); }
__device__ __forceinline__ void cp_wait0()  { asm volatile("cp.async.wait_group 0;\n"); }
__device__ __forceinline__ void cp_wait2()  { asm volatile("cp.async.wait_group 2;\n"); }

__device__ __forceinline__ void mma16816(float* d, const unsigned* a, const unsigned* b) {
    asm volatile(
        "mma.sync.aligned.m16n8k16.row.col.f32.f16.f16.f32 "
        "{%0,%1,%2,%3}, {%4,%5,%6,%7}, {%8,%9}, {%0,%1,%2,%3};\n"
        : "+f"(d[0]), "+f"(d[1]), "+f"(d[2]), "+f"(d[3])
        : "r"(a[0]), "r"(a[1]), "r"(a[2]), "r"(a[3]), "r"(b[0]), "r"(b[1]));
}
__device__ __forceinline__ void ldsm4(unsigned* r, unsigned saddr) {
    asm volatile("ldmatrix.sync.aligned.m8n8.x4.shared.b16 {%0,%1,%2,%3}, [%4];\n"
                 : "=r"(r[0]), "=r"(r[1]), "=r"(r[2]), "=r"(r[3]) : "r"(saddr));
}
__device__ __forceinline__ void ldsm4t(unsigned& r0, unsigned& r1, unsigned& r2, unsigned& r3,
                                       unsigned saddr) {
    asm volatile("ldmatrix.sync.aligned.m8n8.x4.trans.shared.b16 {%0,%1,%2,%3}, [%4];\n"
                 : "=r"(r0), "=r"(r1), "=r"(r2), "=r"(r3) : "r"(saddr));
}
__device__ __forceinline__ unsigned packh2(float a, float b) {
    __half2 h = __floats2half2_rn(a, b);
    return *reinterpret_cast<unsigned*>(&h);
}

template<typename OT> __device__ __forceinline__ void stv(OT* p, float v);
template<> __device__ __forceinline__ void stv<float >(float*  p, float v) { *p = v; }
template<> __device__ __forceinline__ void stv<__half>(__half* p, float v) { *p = __float2half(v); }
template<typename RT> __device__ __forceinline__ float ldv(const RT* p);
template<> __device__ __forceinline__ float ldv<float >(const float*  p) { return *p; }
template<> __device__ __forceinline__ float ldv<__half>(const __half* p) { return __half2float(*p); }

__device__ __forceinline__ void ld8(const float* p, float* v) {
    float4 a = *(const float4*)p, b = *(const float4*)(p + 4);
    v[0]=a.x; v[1]=a.y; v[2]=a.z; v[3]=a.w; v[4]=b.x; v[5]=b.y; v[6]=b.z; v[7]=b.w;
}
__device__ __forceinline__ void ld8(const __half* p, float* v) {
    uint4 u = *(const uint4*)p;
    __half2 h0 = *(__half2*)&u.x, h1 = *(__half2*)&u.y;
    __half2 h2 = *(__half2*)&u.z, h3 = *(__half2*)&u.w;
    float2 f0 = __half22float2(h0), f1 = __half22float2(h1);
    float2 f2 = __half22float2(h2), f3 = __half22float2(h3);
    v[0]=f0.x; v[1]=f0.y; v[2]=f1.x; v[3]=f1.y; v[4]=f2.x; v[5]=f2.y; v[6]=f3.x; v[7]=f3.y;
}
__device__ __forceinline__ void st8h(__half* p, const float* v) {
    uint4 u;
    u.x = packh2(v[0], v[1]); u.y = packh2(v[2], v[3]);
    u.z = packh2(v[4], v[5]); u.w = packh2(v[6], v[7]);
    *(uint4*)p = u;
}
__device__ __forceinline__ float wred(float v) {
#pragma unroll
    for (int s = 16; s > 0; s >>= 1) v += __shfl_xor_sync(0xffffffffu, v, s);
    return v;
}

// ---------------- small kernels ----------------
__global__ void k_embed(const float* __restrict__ mo, const float* __restrict__ e,
                        float* __restrict__ em) {
    int i = blockIdx.x*256 + threadIdx.x;
    if (i < BB*6*DIMM) em[i] = mo[i % EMSTR] + e[i];
}

__global__ void k_ropetab(const float* __restrict__ fc, const float* __restrict__ fs,
                          float* __restrict__ cb, float* __restrict__ sb) {
    int i = blockIdx.x*256 + threadIdx.x;
    if (i >= SS*64) return;
    int s = i >> 6, d = i & 63;
    int f = s >> 8, h = (s >> 4) & 15, w = s & 15;
    int row = (d < 22) ? f : ((d < 43) ? h : w);
    cb[i] = fc[row*64 + d];
    sb[i] = fs[row*64 + d];
}

// fused multi-segment fp32->fp16 convert with strided destinations
#define NSEG 11
struct CvtArgs {
    const float* src[NSEG];
    __half*      dst[NSEG];
    int          end[NSEG];    // cumulative 16-elem chunk end offsets
    int          srow[NSEG];   // src row length (elems)
    int          dstr[NSEG];   // dst row stride (elems)
};
__global__ void k_cvt_all(CvtArgs a, int total_chunks) {
    int ch = blockIdx.x*256 + threadIdx.x;
    if (ch >= total_chunks) return;
    int seg = 0;
#pragma unroll
    for (int i = 0; i < NSEG-1; i++) seg += (ch >= a.end[i]);
    int base = (seg == 0) ? 0 : a.end[seg-1];
    int chl = ch - base;
    int cpr = a.srow[seg] >> 4;               // chunks per row
    int row = chl / cpr, cc = (chl - row*cpr) << 4;
    const float* s = a.src[seg] + (size_t)row*a.srow[seg] + cc;
    __half* d = a.dst[seg] + (size_t)row*a.dstr[seg] + cc;
    float v0[8], v1[8];
    ld8(s, v0); ld8(s + 8, v1);
    st8h(d, v0); st8h(d + 8, v1);
}

// One-pass LayerNorm, warp-shuffle reduction
template<typename IT>
__global__ void k_ln(const IT* __restrict__ x, const float* __restrict__ scv,
                     const float* __restrict__ shv, int em_mode, __half* __restrict__ out) {
    __shared__ float w1s[8], w2s[8];
    int row = blockIdx.x, tid = threadIdx.x;
    int wp = tid >> 5, lane = tid & 31;
    int c0 = tid*8;
    float v[8];
    ld8(x + (size_t)row*DIMM + c0, v);
    float s1 = 0.f, s2 = 0.f;
#pragma unroll
    for (int i = 0; i < 8; i++) { s1 += v[i]; s2 += v[i]*v[i]; }
    s1 = wred(s1); s2 = wred(s2);
    if (lane == 0) { w1s[wp] = s1; w2s[wp] = s2; }
    __syncthreads();
    float t1 = 0.f, t2 = 0.f;
#pragma unroll
    for (int i = 0; i < 8; i++) { t1 += w1s[i]; t2 += w2s[i]; }
    float m = t1 * (1.f/DIMM);
    float inv = rsqrtf(t2*(1.f/DIMM) - m*m + EPSF);
    int bo = (row >> 11) * EMSTR;
    float sc[8], sh[8], o[8];
    if (em_mode) {
        ld8(scv + bo + c0, sc);
        ld8(shv + bo + c0, sh);
#pragma unroll
        for (int i = 0; i < 8; i++) o[i] = (v[i]-m)*inv*(1.f + sc[i]) + sh[i];
    } else {
        ld8(scv + c0, sc);
        ld8(shv + c0, sh);
#pragma unroll
        for (int i = 0; i < 8; i++) o[i] = (v[i]-m)*inv*sc[i] + sh[i];
    }
    st8h(out + (size_t)row*DIMM + c0, o);
}

// One-pass RMS norm + optional RoPE + transpose
__global__ void k_rms_t(const __half* __restrict__ in, const float* __restrict__ w,
                        __half* __restrict__ outT, int L, int do_rope, float oscale) {
    __shared__ float ws[8];
    int row = blockIdx.x, tid = threadIdx.x;
    int wp = tid >> 5, lane = tid & 31;
    int b = row / L, s = row % L;
    int c0 = tid*8;
    float v[8];
    ld8(in + (size_t)row*DIMM + c0, v);
    float s2 = 0.f;
#pragma unroll
    for (int i = 0; i < 8; i++) s2 += v[i]*v[i];
    s2 = wred(s2);
    if (lane == 0) ws[wp] = s2;
    __syncthreads();
    float t2 = 0.f;
#pragma unroll
    for (int i = 0; i < 8; i++) t2 += ws[i];
    float inv = rsqrtf(t2*(1.f/DIMM) + EPSF) * oscale;
    float wv[8], o[8];
    ld8(w + c0, wv);
    int hh = c0 >> 7, hd0 = c0 & 127;
    __half* ob = outT + ((size_t)(b*HEADS + hh)*L + s)*HD + hd0;
    if (do_rope) {
#pragma unroll
        for (int j = 0; j < 4; j++) {
            int i = ((c0 >> 1) + j) & 63;
            float vr = v[2*j]   * wv[2*j]   * inv;
            float vi = v[2*j+1] * wv[2*j+1] * inv;
            float c = g_cos[s*64 + i], sn = g_sin[s*64 + i];
            o[2*j]   = vr*c - vi*sn;
            o[2*j+1] = vr*sn + vi*c;
        }
    } else {
#pragma unroll
        for (int i = 0; i < 8; i++) o[i] = v[i]*inv*wv[i];
    }
    st8h(ob, o);
}

// ---------------- GEMM core macros (shared by both GEMM kernels) ----------------
#define GLDH   40
#define BLDH   136
#define V3_A   (128*GLDH)
#define V3_B   (32*BLDH)
#define V3_STG (V3_A + V3_B)
#define V3_SMEM (4*V3_STG*2)

// generic single-output GEMM (R15 proven core)
template<int EPI, typename RT, typename OT>
__global__ __launch_bounds__(128, 2)
void k_gemm3(const __half* __restrict__ A, const __half* __restrict__ Bw,
             const float* __restrict__ bias, const RT* __restrict__ res,
             const float* __restrict__ gate, OT* __restrict__ C,
             int M, int N, int K) {
    extern __shared__ __half sm[];
    int tid = threadIdx.x;
    int w = tid >> 5, lane = tid & 31;
    int bm = blockIdx.y << 7, bn = blockIdx.x << 7;
    const __half* Ab = A + (size_t)bm*K;

    int wm = (w >> 1)*64, wn = (w & 1)*64;
    int r = lane >> 2, cc = lane & 3;
    int mat = lane >> 3, lr = lane & 7;
    int lrow = (lane & 7) + ((lane >> 3) & 1)*8;
    int lcol = (lane >> 4)*8;

    unsigned aoff[4], boff[4];
#pragma unroll
    for (int mi = 0; mi < 4; mi++)
        aoff[mi] = ((wm + mi*16 + ((mat & 1) << 3) + lr)*GLDH + ((mat >> 1) << 3)) * 2;
#pragma unroll
    for (int nj = 0; nj < 4; nj++)
        boff[nj] = (unsigned)((lrow*BLDH + wn + nj*16 + lcol) * 2);

    float acc[4][8][4];
#pragma unroll
    for (int i = 0; i < 4; i++)
#pragma unroll
        for (int j = 0; j < 8; j++)
#pragma unroll
            for (int t = 0; t < 4; t++) acc[i][j][t] = 0.f;

    auto stage = [&](int s, int kt) {
        __half* As = sm + s*V3_STG;
        __half* Bs = As + V3_A;
        int k0 = kt*32;
#pragma unroll
        for (int i2 = 0; i2 < 4; i2++) {
            int ch = tid + i2*128;
            int arow = ch >> 2, asg = ch & 3;
            cp16(&As[arow*GLDH + asg*8], Ab + (size_t)arow*K + k0 + asg*8);
            int brow = ch >> 4, bsg = ch & 15;
            cp16(&Bs[brow*BLDH + bsg*8], Bw + (size_t)(k0 + brow)*N + bn + bsg*8);
        }
        cp_commit();
    };

    int nk = K >> 5;
    stage(0, 0); stage(1, 1); stage(2, 2);
    for (int kt = 0; kt < nk; kt++) {
        cp_wait2();
        __syncthreads();
        if (kt + 3 < nk) stage((kt+3) & 3, kt+3);
        else             cp_commit();
        int st = kt & 3;
        unsigned abase = (unsigned)__cvta_generic_to_shared(sm + st*V3_STG);
        unsigned bbase = abase + V3_A*2;
#pragma unroll
        for (int ks = 0; ks < 2; ks++) {
            unsigned af[4][4], bf[4][4];
#pragma unroll
            for (int mi = 0; mi < 4; mi++) ldsm4(af[mi], abase + aoff[mi] + ks*32);
#pragma unroll
            for (int nj = 0; nj < 4; nj++)
                ldsm4t(bf[nj][0], bf[nj][1], bf[nj][2], bf[nj][3],
                       bbase + boff[nj] + (unsigned)(ks*16*BLDH*2));
#pragma unroll
            for (int mi = 0; mi < 4; mi++)
#pragma unroll
                for (int nj = 0; nj < 4; nj++) {
                    mma16816(acc[mi][2*nj],     af[mi], &bf[nj][0]);
                    mma16816(acc[mi][2*nj + 1], af[mi], &bf[nj][2]);
                }
        }
    }

#pragma unroll
    for (int mi = 0; mi < 4; mi++) {
        int row0 = bm + wm + mi*16 + r;
#pragma unroll
        for (int nj = 0; nj < 8; nj++) {
            int col0 = bn + wn + nj*8 + 2*cc;
#pragma unroll
            for (int t = 0; t < 4; t++) {
                int rr  = row0 + ((t >> 1) ? 8 : 0);
                int col = col0 + (t & 1);
                float v = acc[mi][nj][t] + bias[col];
                if (EPI == 1) {
                    float u = v;
                    float z = 0.7978845608028654f*(u + 0.044715f*u*u*u);
                    v = __fdividef(u, 1.f + __expf(-2.f*z));
                }
                if (EPI == 2) v += ldv(&res[(size_t)rr*N + col]);
                if (EPI == 3) v = ldv(&res[(size_t)rr*N + col]) + v * gate[(rr >> 11)*EMSTR + col];
                stv(&C[(size_t)rr*N + col], v);
            }
        }
    }
}

// multi-output GEMM: B is N_total wide, outputs routed by 2048-col segment.
struct MOut { __half* o[3]; const float* b[3]; };
__global__ __launch_bounds__(128, 2)
void k_gemm_multi(const __half* __restrict__ A, const __half* __restrict__ Bw,
                  MOut mo, int M, int N, int K) {
    extern __shared__ __half sm[];
    int tid = threadIdx.x;
    int w = tid >> 5, lane = tid & 31;
    int bm = blockIdx.y << 7, bn = blockIdx.x << 7;
    const __half* Ab = A + (size_t)bm*K;

    int wm = (w >> 1)*64, wn = (w & 1)*64;
    int r = lane >> 2, cc = lane & 3;
    int mat = lane >> 3, lr = lane & 7;
    int lrow = (lane & 7) + ((lane >> 3) & 1)*8;
    int lcol = (lane >> 4)*8;

    unsigned aoff[4], boff[4];
#pragma unroll
    for (int mi = 0; mi < 4; mi++)
        aoff[mi] = ((wm + mi*16 + ((mat & 1) << 3) + lr)*GLDH + ((mat >> 1) << 3)) * 2;
#pragma unroll
    for (int nj = 0; nj < 4; nj++)
        boff[nj] = (unsigned)((lrow*BLDH + wn + nj*16 + lcol) * 2);

    float acc[4][8][4];
#pragma unroll
    for (int i = 0; i < 4; i++)
#pragma unroll
        for (int j = 0; j < 8; j++)
#pragma unroll
            for (int t = 0; t < 4; t++) acc[i][j][t] = 0.f;

    auto stage = [&](int s, int kt) {
        __half* As = sm + s*V3_STG;
        __half* Bs = As + V3_A;
        int k0 = kt*32;
#pragma unroll
        for (int i2 = 0; i2 < 4; i2++) {
            int ch = tid + i2*128;
            int arow = ch >> 2, asg = ch & 3;
            cp16(&As[arow*GLDH + asg*8], Ab + (size_t)arow*K + k0 + asg*8);
            int brow = ch >> 4, bsg = ch & 15;
            cp16(&Bs[brow*BLDH + bsg*8], Bw + (size_t)(k0 + brow)*N + bn + bsg*8);
        }
        cp_commit();
    };

    int nk = K >> 5;
    stage(0, 0); stage(1, 1); stage(2, 2);
    for (int kt = 0; kt < nk; kt++) {
        cp_wait2();
        __syncthreads();
        if (kt + 3 < nk) stage((kt+3) & 3, kt+3);
        else             cp_commit();
        int st = kt & 3;
        unsigned abase = (unsigned)__cvta_generic_to_shared(sm + st*V3_STG);
        unsigned bbase = abase + V3_A*2;
#pragma unroll
        for (int ks = 0; ks < 2; ks++) {
            unsigned af[4][4], bf[4][4];
#pragma unroll
            for (int mi = 0; mi < 4; mi++) ldsm4(af[mi], abase + aoff[mi] + ks*32);
#pragma unroll
            for (int nj = 0; nj < 4; nj++)
                ldsm4t(bf[nj][0], bf[nj][1], bf[nj][2], bf[nj][3],
                       bbase + boff[nj] + (unsigned)(ks*16*BLDH*2));
#pragma unroll
            for (int mi = 0; mi < 4; mi++)
#pragma unroll
                for (int nj = 0; nj < 4; nj++) {
                    mma16816(acc[mi][2*nj],     af[mi], &bf[nj][0]);
                    mma16816(acc[mi][2*nj + 1], af[mi], &bf[nj][2]);
                }
        }
    }

    // epilogue: whole CTA tile lives in one 2048-col segment (2048 % 128 == 0)
    int seg = bn >> 11;
    __half* Cb = mo.o[seg];
    const float* bb = mo.b[seg];
    int bnL = bn - (seg << 11);
#pragma unroll
    for (int mi = 0; mi < 4; mi++) {
        int row0 = bm + wm + mi*16 + r;
#pragma unroll
        for (int nj = 0; nj < 8; nj++) {
            int col0 = bnL + wn + nj*8 + 2*cc;
#pragma unroll
            for (int t = 0; t < 4; t++) {
                int rr  = row0 + ((t >> 1) ? 8 : 0);
                int col = col0 + (t & 1);
                float v = acc[mi][nj][t] + bb[col];
                Cb[(size_t)rr*DIMM + col] = __float2half(v);
            }
        }
    }
}

// ---------------- fp16 flash attention (unchanged from R15) ----------------
#define AT_LDS 136
#define KVSZ   (64*AT_LDS)
#define ATTN_H_SMEM (4*KVSZ*2)
__global__ __launch_bounds__(128)
void k_attn_h(const __half* __restrict__ qt, const __half* __restrict__ kt,
              const __half* __restrict__ vh, __half* __restrict__ y, int Lk) {
    extern __shared__ __half smh[];
    __half* Kb = smh;
    __half* Vb = smh + 2*KVSZ;

    int tid = threadIdx.x;
    int w = tid >> 5, lane = tid & 31;
    int r = lane >> 2, cc = lane & 3;
    int qtile = blockIdx.x, hh = blockIdx.y, b = blockIdx.z;

    const __half* qb = qt + ((size_t)(b*HEADS + hh)*SS + qtile*64) * HD;
    const __half* kb = kt + (size_t)(b*HEADS + hh)*Lk*HD;
    const __half* vb = vh + (size_t)b*Lk*DIMM + hh*HD;

    auto stage_kv = [&](int st, int t2) {
        __half* Kd = Kb + st*KVSZ;
        __half* Vd = Vb + st*KVSZ;
#pragma unroll
        for (int i2 = 0; i2 < 8; i2++) {
            int ch = tid + i2*128;
            int row = ch >> 4, sg = ch & 15;
            cp16(&Kd[row*AT_LDS + sg*8], kb + (size_t)(t2*64 + row)*HD + sg*8);
            cp16(&Vd[row*AT_LDS + sg*8], vb + (size_t)(t2*64 + row)*DIMM + sg*8);
        }
        cp_commit();
    };

    {
        __half* Qd = Kb + KVSZ;
#pragma unroll
        for (int i2 = 0; i2 < 8; i2++) {
            int ch = tid + i2*128;
            int row = ch >> 4, sg = ch & 15;
            cp16(&Qd[row*AT_LDS + sg*8], qb + (size_t)row*HD + sg*8);
        }
        stage_kv(0, 0);
    }
    cp_wait0();
    __syncthreads();

    unsigned afrq[8][4];
    {
        const __half* Qs = Kb + KVSZ;
#pragma unroll
        for (int kc = 0; kc < 8; kc++) {
            int row = w*16 + r, col = kc*16 + 2*cc;
            afrq[kc][0] = *(const unsigned*)&Qs[row*AT_LDS + col];
            afrq[kc][1] = *(const unsigned*)&Qs[(row+8)*AT_LDS + col];
            afrq[kc][2] = *(const unsigned*)&Qs[row*AT_LDS + col + 8];
            afrq[kc][3] = *(const unsigned*)&Qs[(row+8)*AT_LDS + col + 8];
        }
    }

    float acc[16][4];
#pragma unroll
    for (int i = 0; i < 16; i++)
#pragma unroll
        for (int t = 0; t < 4; t++) acc[i][t] = 0.f;
    float m0 = -1e30f, m1 = -1e30f, l0 = 0.f, l1 = 0.f;

    int ntiles = Lk >> 6;
    for (int t2 = 0; t2 < ntiles; t2++) {
        if (t2 > 0) cp_wait0();
        __syncthreads();
        if (t2 + 1 < ntiles) stage_kv((t2+1) & 1, t2+1);
        const __half* Ks = Kb + (t2&1)*KVSZ;
        const __half* Vs = Vb + (t2&1)*KVSZ;

        float sacc[8][4];
#pragma unroll
        for (int nb = 0; nb < 8; nb++)
#pragma unroll
            for (int t = 0; t < 4; t++) sacc[nb][t] = 0.f;
#pragma unroll
        for (int kc = 0; kc < 8; kc++) {
            unsigned bfr[8][2];
            int col = kc*16 + 2*cc;
#pragma unroll
            for (int nb = 0; nb < 8; nb++) {
                int krow = nb*8 + r;
                bfr[nb][0] = *(const unsigned*)&Ks[krow*AT_LDS + col];
                bfr[nb][1] = *(const unsigned*)&Ks[krow*AT_LDS + col + 8];
            }
#pragma unroll
            for (int nb = 0; nb < 8; nb++) mma16816(sacc[nb], afrq[kc], bfr[nb]);
        }

        float mx0 = -1e30f, mx1 = -1e30f;
#pragma unroll
        for (int nb = 0; nb < 8; nb++) {
            mx0 = fmaxf(mx0, fmaxf(sacc[nb][0], sacc[nb][1]));
            mx1 = fmaxf(mx1, fmaxf(sacc[nb][2], sacc[nb][3]));
        }
        mx0 = fmaxf(mx0, __shfl_xor_sync(0xffffffffu, mx0, 1));
        mx0 = fmaxf(mx0, __shfl_xor_sync(0xffffffffu, mx0, 2));
        mx1 = fmaxf(mx1, __shfl_xor_sync(0xffffffffu, mx1, 1));
        mx1 = fmaxf(mx1, __shfl_xor_sync(0xffffffffu, mx1, 2));
        float mn0 = fmaxf(m0, mx0), mn1 = fmaxf(m1, mx1);
        float esc0 = __expf(m0 - mn0), esc1 = __expf(m1 - mn1);
        m0 = mn0; m1 = mn1;
        float ls0 = 0.f, ls1 = 0.f;
#pragma unroll
        for (int nb = 0; nb < 8; nb++) {
            sacc[nb][0] = __expf(sacc[nb][0] - mn0); ls0 += sacc[nb][0];
            sacc[nb][1] = __expf(sacc[nb][1] - mn0); ls0 += sacc[nb][1];
            sacc[nb][2] = __expf(sacc[nb][2] - mn1); ls1 += sacc[nb][2];
            sacc[nb][3] = __expf(sacc[nb][3] - mn1); ls1 += sacc[nb][3];
        }
        ls0 += __shfl_xor_sync(0xffffffffu, ls0, 1);
        ls0 += __shfl_xor_sync(0xffffffffu, ls0, 2);
        ls1 += __shfl_xor_sync(0xffffffffu, ls1, 1);
        ls1 += __shfl_xor_sync(0xffffffffu, ls1, 2);
        l0 = l0*esc0 + ls0;
        l1 = l1*esc1 + ls1;

        unsigned pf[4][4];
#pragma unroll
        for (int kc = 0; kc < 4; kc++) {
            pf[kc][0] = packh2(sacc[2*kc][0],   sacc[2*kc][1]);
            pf[kc][1] = packh2(sacc[2*kc][2],   sacc[2*kc][3]);
            pf[kc][2] = packh2(sacc[2*kc+1][0], sacc[2*kc+1][1]);
            pf[kc][3] = packh2(sacc[2*kc+1][2], sacc[2*kc+1][3]);
        }
#pragma unroll
        for (int nb = 0; nb < 16; nb++) {
            acc[nb][0] *= esc0; acc[nb][1] *= esc0;
            acc[nb][2] *= esc1; acc[nb][3] *= esc1;
        }

        unsigned vbase = (unsigned)__cvta_generic_to_shared(Vs);
        int lrow = (lane & 7) + ((lane >> 3) & 1)*8;
        int lcol = (lane >> 4)*8;
#pragma unroll
        for (int np = 0; np < 8; np++) {
#pragma unroll
            for (int kc = 0; kc < 4; kc++) {
                unsigned r0, r1, r2, r3;
                unsigned addr = vbase + (unsigned)(((kc*16 + lrow)*AT_LDS + np*16 + lcol)*2);
                ldsm4t(r0, r1, r2, r3, addr);
                unsigned b0[2] = {r0, r1};
                unsigned b1[2] = {r2, r3};
                mma16816(acc[np*2],     pf[kc], b0);
                mma16816(acc[np*2 + 1], pf[kc], b1);
            }
        }
    }

    float inv0 = 1.f/l0, inv1 = 1.f/l1;
    int row0 = qtile*64 + w*16 + r;
    __half* yb = y + (size_t)b*SS*DIMM + hh*HD;
#pragma unroll
    for (int nb = 0; nb < 16; nb++) {
        int col = nb*8 + 2*cc;
        __half2 h0 = __floats2half2_rn(acc[nb][0]*inv0, acc[nb][1]*inv0);
        __half2 h1 = __floats2half2_rn(acc[nb][2]*inv1, acc[nb][3]*inv1);
        *(__half2*)&yb[(size_t)row0*DIMM + col]     = h0;
        *(__half2*)&yb[(size_t)(row0+8)*DIMM + col] = h1;
    }
}

// ---------------- host ----------------
extern "C" void kernel_launch(void* const* d_in, const int* in_sizes, int n_in,
                              void* d_out, int out_size) {
    const float* x       = (const float*)d_in[0];
    const float* e       = (const float*)d_in[1];
    const float* context = (const float*)d_in[2];
    const float* fcos    = (const float*)d_in[3];
    const float* fsin    = (const float*)d_in[4];
    const float* modu    = (const float*)d_in[5];
    const float* sa_wq = (const float*)d_in[6];  const float* sa_bq = (const float*)d_in[7];
    const float* sa_wk = (const float*)d_in[8];  const float* sa_bk = (const float*)d_in[9];
    const float* sa_wv = (const float*)d_in[10]; const float* sa_bv = (const float*)d_in[11];
    const float* sa_wo = (const float*)d_in[12]; const float* sa_bo = (const float*)d_in[13];
    const float* sa_nq = (const float*)d_in[14]; const float* sa_nk = (const float*)d_in[15];
    const float* ca_wq = (const float*)d_in[16]; const float* ca_bq = (const float*)d_in[17];
    const float* ca_wk = (const float*)d_in[18]; const float* ca_bk = (const float*)d_in[19];
    const float* ca_wv = (const float*)d_in[20]; const float* ca_bv = (const float*)d_in[21];
    const float* ca_wo = (const float*)d_in[22]; const float* ca_bo = (const float*)d_in[23];
    const float* ca_nq = (const float*)d_in[24]; const float* ca_nk = (const float*)d_in[25];
    const float* n3_w  = (const float*)d_in[26]; const float* n3_b  = (const float*)d_in[27];
    const float* w1    = (const float*)d_in[28]; const float* b1    = (const float*)d_in[29];
    const float* w2    = (const float*)d_in[30]; const float* b2    = (const float*)d_in[31];
    float* out = (float*)d_out;

    float *em, *cb, *sb2;
    __half *xbh, *tmph, *qh, *kh, *vhp, *xn, *y, *h, *ctxh, *wt;
    cudaGetSymbolAddress((void**)&em,   g_em);
    cudaGetSymbolAddress((void**)&cb,   g_cos);
    cudaGetSymbolAddress((void**)&sb2,  g_sin);
    cudaGetSymbolAddress((void**)&xbh,  g_xb);
    cudaGetSymbolAddress((void**)&tmph, g_tmp);
    cudaGetSymbolAddress((void**)&qh,   g_qh);
    cudaGetSymbolAddress((void**)&kh,   g_kh);
    cudaGetSymbolAddress((void**)&vhp,  g_vh);
    cudaGetSymbolAddress((void**)&xn,   g_xn);
    cudaGetSymbolAddress((void**)&y,    g_y);
    cudaGetSymbolAddress((void**)&h,    g_h);
    cudaGetSymbolAddress((void**)&ctxh, g_ctx);
    cudaGetSymbolAddress((void**)&wt,   g_wt);

    cudaFuncSetAttribute(k_attn_h, cudaFuncAttributeMaxDynamicSharedMemorySize, ATTN_H_SMEM);
    cudaFuncSetAttribute((const void*)k_gemm_multi,              cudaFuncAttributeMaxDynamicSharedMemorySize, V3_SMEM);
    cudaFuncSetAttribute((const void*)k_gemm3<0,float,__half>,   cudaFuncAttributeMaxDynamicSharedMemorySize, V3_SMEM);
    cudaFuncSetAttribute((const void*)k_gemm3<1,float,__half>,   cudaFuncAttributeMaxDynamicSharedMemorySize, V3_SMEM);
    cudaFuncSetAttribute((const void*)k_gemm3<2,__half,__half>,  cudaFuncAttributeMaxDynamicSharedMemorySize, V3_SMEM);
    cudaFuncSetAttribute((const void*)k_gemm3<3,float,__half>,   cudaFuncAttributeMaxDynamicSharedMemorySize, V3_SMEM);
    cudaFuncSetAttribute((const void*)k_gemm3<3,__half,float>,   cudaFuncAttributeMaxDynamicSharedMemorySize, V3_SMEM);

    const float QSC = 0.08838834764831845f;

    dim3 blk(256);
    dim3 gblk(128);
    dim3 gQKV(6144/128, M1/128);     // (48, 32)
    dim3 gCKV(4096/128, MC/128);     // (32, 8)
    dim3 gP(DIMM/128, M1/128);
    dim3 gC(DIMM/128, MC/128);
    dim3 gF1(FFN/128, M1/128);
    dim3 gF2(DIMM/128, M1/128);
    dim3 gA(SS/64, HEADS, BB);

    const int NW = DIMM*DIMM;
    const int NF = DIMM*FFN;

    // ---- fused pre-pass convert (strided destinations for concatenated weights) ----
    {
        CvtArgs a;
        const float* srcs[NSEG] = { sa_wq, sa_wk, sa_wv, sa_wo, ca_wq, ca_wk, ca_wv, ca_wo,
                                    w1, w2, context };
        __half* dsts[NSEG] = { wt+OFF_QKV, wt+OFF_QKV+2048, wt+OFF_QKV+4096, wt+OFF_O,
                               wt+OFF_CQ, wt+OFF_CKV, wt+OFF_CKV+2048, wt+OFF_CO,
                               wt+OFF_F1, wt+OFF_F2, ctxh };
        int sizes[NSEG]  = { NW, NW, NW, NW, NW, NW, NW, NW, NF, NF, MC*DIMM };
        int srows[NSEG]  = { 2048, 2048, 2048, 2048, 2048, 2048, 2048, 2048, 8192, 2048, 2048 };
        int dstrs[NSEG]  = { 6144, 6144, 6144, 2048, 2048, 4096, 4096, 2048, 8192, 2048, 2048 };
        int cum = 0;
        for (int i = 0; i < NSEG; i++) {
            a.src[i] = srcs[i]; a.dst[i] = dsts[i];
            a.srow[i] = srows[i]; a.dstr[i] = dstrs[i];
            cum += sizes[i] / 16;
            a.end[i] = cum;
        }
        int total = cum;
        k_cvt_all<<<(total + 255)/256, blk>>>(a, total);
    }
    k_embed<<<(BB*6*DIMM + 255)/256, blk>>>(modu, e, em);
    k_ropetab<<<(SS*64 + 255)/256, blk>>>(fcos, fsin, cb, sb2);

    // ---- self attention ----
    k_ln<float><<<M1, blk>>>(x, em + 1*DIMM, em + 0*DIMM, 1, xn);
    {
        MOut mo; mo.o[0] = tmph; mo.o[1] = y; mo.o[2] = vhp;
        mo.b[0] = sa_bq; mo.b[1] = sa_bk; mo.b[2] = sa_bv;
        k_gemm_multi<<<gQKV, gblk, V3_SMEM>>>(xn, wt + OFF_QKV, mo, M1, 6144, DIMM);
    }
    k_rms_t<<<M1, blk>>>(tmph, sa_nq, qh, SS, 1, QSC);
    k_rms_t<<<M1, blk>>>(y,    sa_nk, kh, SS, 1, 1.f);
    k_attn_h<<<gA, gblk, ATTN_H_SMEM>>>(qh, kh, vhp, y, SS);
    k_gemm3<3,float,__half><<<gP, gblk, V3_SMEM>>>(y, wt + OFF_O, sa_bo, x, em + 2*DIMM, xbh, M1, DIMM, DIMM);

    // ---- cross attention ----
    k_ln<__half><<<M1, blk>>>(xbh, n3_w, n3_b, 0, xn);
    k_gemm3<0,float,__half><<<gP, gblk, V3_SMEM>>>(xn, wt + OFF_CQ, ca_bq, nullptr, nullptr, tmph, M1, DIMM, DIMM);
    k_rms_t<<<M1, blk>>>(tmph, ca_nq, qh, SS, 0, QSC);
    {
        MOut mo; mo.o[0] = y; mo.o[1] = vhp; mo.o[2] = nullptr;
        mo.b[0] = ca_bk; mo.b[1] = ca_bv; mo.b[2] = nullptr;
        k_gemm_multi<<<gCKV, gblk, V3_SMEM>>>(ctxh, wt + OFF_CKV, mo, MC, 4096, DIMM);
    }
    k_rms_t<<<MC, blk>>>(y, ca_nk, kh, CTX, 0, 1.f);
    k_attn_h<<<gA, gblk, ATTN_H_SMEM>>>(qh, kh, vhp, y, CTX);
    k_gemm3<2,__half,__half><<<gP, gblk, V3_SMEM>>>(y, wt + OFF_CO, ca_bo, xbh, nullptr, xbh, M1, DIMM, DIMM);

    // ---- FFN ----
    k_ln<__half><<<M1, blk>>>(xbh, em + 4*DIMM, em + 3*DIMM, 1, xn);
    k_gemm3<1,float,__half><<<gF1, gblk, V3_SMEM>>>(xn, wt + OFF_F1, b1, nullptr, nullptr, h, M1, FFN, DIMM);
    k_gemm3<3,__half,float><<<gF2, gblk, V3_SMEM>>>(h, wt + OFF_F2, b2, xbh, em + 5*DIMM, out, M1, DIMM, FFN);
}